// round 1
// baseline (speedup 1.0000x reference)
#include <cuda_runtime.h>
#include <cstddef>

#define B_   16
#define CI_  64
#define CO_  64
#define N_   128          // H == W
#define M_   20
#define HW_  (N_*N_)      // 16384
#define MODES_ (M_*M_)    // 400
#define BC_  (B_*CI_)     // 1024
#define BO_  (B_*CO_)     // 1024
#define NC_  73           // computed W-columns: 0..36 and 92..127

// Scratch (allocation-free contract -> __device__ globals)
__device__ float g_Xh[BC_*MODES_];
__device__ float g_Z [BO_*MODES_];
__device__ float g_buf0[(size_t)BO_*HW_];
__device__ float g_buf1[(size_t)BO_*HW_];

__device__ __forceinline__ void fill_tabs(float* ct, float* st) {
    const float w = 6.283185307179586f / 128.0f;
    for (int t = threadIdx.x; t < 128; t += blockDim.x) {
        float s, c;
        sincosf(w * (float)t, &s, &c);
        ct[t] = c; st[t] = s;
    }
}

__device__ __forceinline__ void gauss9(float* g) {
    float s = 0.f;
#pragma unroll
    for (int i = 0; i < 9; ++i) {
        float d = (float)(i - 4);
        g[i] = expf(-0.5f * d * d);
        s += g[i];
    }
    float inv = 1.0f / s;
#pragma unroll
    for (int i = 0; i < 9; ++i) g[i] *= inv;
}

// ---------------------------------------------------------------------------
// K1: truncated forward "DHT": x[bc,128,128] -> Xh[bc,20,20]
// Xh[k1,k2] = sum_{n1,n2} x * [cos(2pi(k1 n1 + k2 n2)/128) - sin(2pi(k1(n1+1)+k2(n2+1))/128)]
// Separable: stage1 (over n2) gives U=cos-proj, V=sin-proj; primed versions are
// per-k2 rotations of (U,V). Stage2 contracts over n1 with per-k1 rotations.
// ---------------------------------------------------------------------------
__global__ void __launch_bounds__(256) k_fwd(const float* __restrict__ x) {
    __shared__ float ct[128], st[128];
    __shared__ float xs[32][129];
    __shared__ float U[128][20], V[128][20];

    int bc = blockIdx.x;
    const float* xp = x + (size_t)bc * HW_;
    fill_tabs(ct, st);

    for (int ch = 0; ch < 4; ++ch) {
        __syncthreads();
        for (int idx = threadIdx.x; idx < 32*128; idx += 256) {
            int r = idx >> 7, n2 = idx & 127;
            xs[r][n2] = xp[(ch*32 + r)*128 + n2];
        }
        __syncthreads();
        // 320 tasks: 20 k2 x 16 row-pairs
        for (int task = threadIdx.x; task < 320; task += 256) {
            int k2 = task % 20;
            int rp = task / 20;
            int r0 = rp*2, r1 = r0 + 1;
            float u0=0.f, v0=0.f, u1=0.f, v1=0.f;
            int t = 0;
#pragma unroll 8
            for (int n2 = 0; n2 < 128; ++n2) {
                float c = ct[t], s = st[t];
                float a = xs[r0][n2], b = xs[r1][n2];
                u0 += a*c; v0 += a*s;
                u1 += b*c; v1 += b*s;
                t = (t + k2) & 127;
            }
            int n1 = ch*32;
            U[n1+r0][k2] = u0; V[n1+r0][k2] = v0;
            U[n1+r1][k2] = u1; V[n1+r1][k2] = v1;
        }
    }
    __syncthreads();

    float* out = g_Xh + (size_t)bc * MODES_;
    for (int o = threadIdx.x; o < MODES_; o += 256) {
        int k1 = o / 20, k2 = o % 20;
        float cd = ct[k2], sd = st[k2];   // rotation by 2*pi*k2/128
        float acc = 0.f;
        int t = 0;                        // t = (k1*n1) mod 128
#pragma unroll 4
        for (int n1 = 0; n1 < 128; ++n1) {
            int tp = (t + k1) & 127;      // (k1*(n1+1)) mod 128
            float u = U[n1][k2], v = V[n1][k2];
            float ub = cd*u - sd*v;       // primed cos-projection
            float vb = sd*u + cd*v;       // primed sin-projection
            acc += ct[t]*u - st[t]*v - st[tp]*ub - ct[tp]*vb;
            t = tp;
        }
        out[o] = acc;
    }
}

// ---------------------------------------------------------------------------
// K2: compl_mul2d folded: Out = e(X, Wp) + e(Xneg, Wm),
// Wp = 0.5*(w + w_negk), Wm = 0.5*(w - w_negk). One block per (m1,m2) mode.
// ---------------------------------------------------------------------------
__global__ void __launch_bounds__(256) k_mul(const float* __restrict__ w1) {
    __shared__ float Xs[1024], Xn[1024], Wp[4096], Wm[4096];
    int m  = blockIdx.x;
    int m1 = m / 20, m2 = m % 20;
    int mn = ((20 - m1) % 20) * 20 + ((20 - m2) % 20);

    for (int i = threadIdx.x; i < 1024; i += 256) {
        Xs[i] = g_Xh[(size_t)i * MODES_ + m];
        Xn[i] = g_Xh[(size_t)i * MODES_ + mn];
    }
    for (int i = threadIdx.x; i < 4096; i += 256) {
        float w  = w1[(size_t)i * MODES_ + m];
        float wn = w1[(size_t)i * MODES_ + mn];
        Wp[i] = 0.5f * (w + wn);
        Wm[i] = 0.5f * (w - wn);
    }
    __syncthreads();

    for (int p = threadIdx.x; p < 1024; p += 256) {
        int b = p >> 6, o = p & 63;
        const float* xb  = Xs + b*64;
        const float* xnb = Xn + b*64;
        float acc = 0.f;
#pragma unroll 8
        for (int i = 0; i < 64; ++i)
            acc += xb[i]*Wp[i*64 + o] + xnb[i]*Wm[i*64 + o];
        g_Z[(size_t)p * MODES_ + m] = acc;
    }
}

// ---------------------------------------------------------------------------
// K3: inverse transform (modes 20x20 -> spatial 128x128), scaled by 1/(H*W).
// Only the 73 W-columns that survive the final mask (+blur halo) are computed:
// n2 in [0,36] U [92,127]. One block per (b,o).
// ---------------------------------------------------------------------------
__global__ void __launch_bounds__(256) k_inv(void) {
    __shared__ float ct[128], st[128];
    __shared__ float Zs[400];
    __shared__ float G1[20*NC_], G2[20*NC_], P1[20*NC_], P2[20*NC_];

    int bo = blockIdx.x;
    fill_tabs(ct, st);
    for (int i = threadIdx.x; i < 400; i += 256)
        Zs[i] = g_Z[(size_t)bo * MODES_ + i];
    __syncthreads();

    // Stage 1: contract over m2 for each (m1, column j)
    for (int idx = threadIdx.x; idx < 20*NC_; idx += 256) {
        int m1 = idx % 20;
        int j  = idx / 20;
        int n2 = (j < 37) ? j : j + 55;
        const float* zr = Zs + m1*20;
        float g1 = 0.f, g2 = 0.f;
        int t = 0;                          // (n2*m2) mod 128
#pragma unroll
        for (int m2 = 0; m2 < 20; ++m2) {
            float z = zr[m2];
            g1 += z * ct[t];
            g2 += z * st[t];
            t = (t + n2) & 127;
        }
        float cb = ct[n2], sb = st[n2];     // rotation by 2*pi*n2/128
        G1[m1*NC_ + j] = g1;
        G2[m1*NC_ + j] = g2;
        P1[m1*NC_ + j] = cb*g1 - sb*g2;     // primed cos-projection
        P2[m1*NC_ + j] = sb*g1 + cb*g2;     // primed sin-projection
    }
    __syncthreads();

    const float inv = 1.0f / 16384.0f;
    float* out = g_buf0 + (size_t)bo * HW_;
    for (int idx = threadIdx.x; idx < 128*NC_; idx += 256) {
        int n1 = idx / NC_, j = idx % NC_;
        int n2 = (j < 37) ? j : j + 55;
        float acc = 0.f;
        int t = 0;                          // (n1*m1) mod 128
#pragma unroll
        for (int m1 = 0; m1 < 20; ++m1) {
            int tp = (t + n1) & 127;        // (n1*(m1+1)) mod 128
            acc += ct[t]*G1[m1*NC_+j] - st[t]*G2[m1*NC_+j]
                 - st[tp]*P1[m1*NC_+j] - ct[tp]*P2[m1*NC_+j];
            t = tp;
        }
        out[n1*128 + n2] = acc * inv;
    }
}

// ---------------------------------------------------------------------------
// K4: W-axis 9-tap Gaussian (edge clamp) + low-pass mask. Masked-out columns
// are written as 0, so they stay 0 through the remaining (H,B,C) blurs.
// ---------------------------------------------------------------------------
__global__ void __launch_bounds__(256) k_wblur(void) {
    __shared__ float rows[2][128];
    int tid = threadIdx.x;
    int r = tid >> 7, w = tid & 127;
    size_t row = (size_t)blockIdx.x * 2 + r;
    rows[r][w] = g_buf0[row * 128 + w];
    __syncthreads();

    float acc = 0.f;
    if (w <= 32 || w >= 96) {
        float gk[9]; gauss9(gk);
#pragma unroll
        for (int t = 0; t < 9; ++t) {
            int ww = w + t - 4;
            ww = ww < 0 ? 0 : (ww > 127 ? 127 : ww);
            acc += gk[t] * rows[r][ww];
        }
    }
    g_buf1[row * 128 + w] = acc;
}

// ---------------------------------------------------------------------------
// K5: H-axis blur. Block = one (b,c) plane chunk of 16 rows + halo in smem.
// ---------------------------------------------------------------------------
__global__ void __launch_bounds__(256) k_hblur(void) {
    __shared__ float tile[24][128];
    int bc = blockIdx.x >> 3;
    int h0 = (blockIdx.x & 7) * 16;
    const float* in = g_buf1 + (size_t)bc * HW_;
    for (int idx = threadIdx.x; idx < 24*128; idx += 256) {
        int r = idx >> 7, w = idx & 127;
        int h = h0 + r - 4;
        h = h < 0 ? 0 : (h > 127 ? 127 : h);
        tile[r][w] = in[h*128 + w];
    }
    __syncthreads();

    float gk[9]; gauss9(gk);
    float* outp = g_buf0 + (size_t)bc * HW_;
    for (int idx = threadIdx.x; idx < 16*128; idx += 256) {
        int r = idx >> 7, w = idx & 127;
        float acc = 0.f;
#pragma unroll
        for (int t = 0; t < 9; ++t) acc += gk[t] * tile[r + t][w];
        outp[(h0 + r)*128 + w] = acc;
    }
}

// ---------------------------------------------------------------------------
// K6: B-axis blur (B=16). Each thread owns one (c,h,w) and the full B-line.
// ---------------------------------------------------------------------------
__global__ void __launch_bounds__(256) k_bblur(void) {
    size_t p = (size_t)blockIdx.x * 256 + threadIdx.x;   // over CO_*HW_ = 1048576
    float v[16];
#pragma unroll
    for (int b = 0; b < 16; ++b)
        v[b] = g_buf0[(size_t)b * ((size_t)CO_*HW_) + p];
    float gk[9]; gauss9(gk);
#pragma unroll
    for (int b = 0; b < 16; ++b) {
        float acc = 0.f;
#pragma unroll
        for (int t = 0; t < 9; ++t) {
            int bb = b + t - 4;
            bb = bb < 0 ? 0 : (bb > 15 ? 15 : bb);
            acc += gk[t] * v[bb];
        }
        g_buf1[(size_t)b * ((size_t)CO_*HW_) + p] = acc;
    }
}

// ---------------------------------------------------------------------------
// K7: C-axis blur (C=64) via sliding window, writes final output.
// ---------------------------------------------------------------------------
__global__ void __launch_bounds__(256) k_cblur(float* __restrict__ out) {
    int idx = blockIdx.x * 256 + threadIdx.x;            // over B_*HW_ = 262144
    int b  = idx >> 14;
    int hw = idx & 16383;
    const float* in = g_buf1 + (size_t)b * ((size_t)CO_*HW_) + hw;
    float* op       = out    + (size_t)b * ((size_t)CO_*HW_) + hw;

    float gk[9]; gauss9(gk);
    float win[9];
#pragma unroll
    for (int t = 0; t < 9; ++t) {
        int c = t - 4; c = c < 0 ? 0 : c;
        win[t] = in[(size_t)c * HW_];
    }
    for (int c = 0; c < 64; ++c) {
        float acc = 0.f;
#pragma unroll
        for (int t = 0; t < 9; ++t) acc += gk[t] * win[t];
        op[(size_t)c * HW_] = acc;
#pragma unroll
        for (int t = 0; t < 8; ++t) win[t] = win[t+1];
        int cn = c + 5; cn = cn > 63 ? 63 : cn;
        win[8] = in[(size_t)cn * HW_];
    }
}

extern "C" void kernel_launch(void* const* d_in, const int* in_sizes, int n_in,
                              void* d_out, int out_size) {
    (void)in_sizes; (void)n_in; (void)out_size;
    const float* x  = (const float*)d_in[0];
    const float* w1 = (const float*)d_in[1];
    float* out = (float*)d_out;

    k_fwd  <<<BC_,        256>>>(x);     // x -> Xh[1024,20,20]
    k_mul  <<<MODES_,     256>>>(w1);    // Xh,w1 -> Z[1024,20,20]
    k_inv  <<<BO_,        256>>>();      // Z -> buf0 (73 W-cols valid)
    k_wblur<<<BO_*N_/2,   256>>>();      // buf0 -> buf1 (W blur + mask)
    k_hblur<<<BO_*8,      256>>>();      // buf1 -> buf0 (H blur)
    k_bblur<<<CO_*HW_/256,256>>>();      // buf0 -> buf1 (B blur)
    k_cblur<<<B_*HW_/256, 256>>>(out);   // buf1 -> out  (C blur)
}

// round 2
// speedup vs baseline: 1.0059x; 1.0059x over previous
#include <cuda_runtime.h>
#include <cstddef>

#define B_   16
#define CI_  64
#define CO_  64
#define N_   128          // H == W
#define M_   20
#define HW_  (N_*N_)      // 16384
#define MODES_ (M_*M_)    // 400
#define BC_  (B_*CI_)     // 1024
#define BO_  (B_*CO_)     // 1024
#define NC_  73           // computed W-columns: 0..36 and 92..127

// Scratch (allocation-free contract -> __device__ globals)
__device__ float g_Xh[BC_*MODES_];
__device__ float g_Z [BO_*MODES_];
__device__ float g_buf0[(size_t)BO_*HW_];
__device__ float g_buf1[(size_t)BO_*HW_];

__device__ __forceinline__ void fill_tabs(float* ct, float* st) {
    const float w = 6.283185307179586f / 128.0f;
    for (int t = threadIdx.x; t < 128; t += blockDim.x) {
        float s, c;
        sincosf(w * (float)t, &s, &c);
        ct[t] = c; st[t] = s;
    }
}

__device__ __forceinline__ void gauss9(float* g) {
    float s = 0.f;
#pragma unroll
    for (int i = 0; i < 9; ++i) {
        float d = (float)(i - 4);
        g[i] = expf(-0.5f * d * d);
        s += g[i];
    }
    float inv = 1.0f / s;
#pragma unroll
    for (int i = 0; i < 9; ++i) g[i] *= inv;
}

// ---------------------------------------------------------------------------
// K1: truncated forward "DHT": x[bc,128,128] -> Xh[bc,20,20]
// Xh[k1,k2] = sum_{n1,n2} x * [cos(2pi(k1 n1 + k2 n2)/128) - sin(2pi(k1(n1+1)+k2(n2+1))/128)]
// Separable: stage1 (over n2) gives U=cos-proj, V=sin-proj; primed versions are
// per-k2 rotations of (U,V). Stage2 contracts over n1 with per-k1 rotations.
// ---------------------------------------------------------------------------
__global__ void __launch_bounds__(256) k_fwd(const float* __restrict__ x) {
    __shared__ float ct[128], st[128];
    __shared__ float xs[32][129];
    __shared__ float U[128][20], V[128][20];

    int bc = blockIdx.x;
    const float* xp = x + (size_t)bc * HW_;
    fill_tabs(ct, st);

    for (int ch = 0; ch < 4; ++ch) {
        __syncthreads();
        for (int idx = threadIdx.x; idx < 32*128; idx += 256) {
            int r = idx >> 7, n2 = idx & 127;
            xs[r][n2] = xp[(ch*32 + r)*128 + n2];
        }
        __syncthreads();
        // 320 tasks: 20 k2 x 16 row-pairs
        for (int task = threadIdx.x; task < 320; task += 256) {
            int k2 = task % 20;
            int rp = task / 20;
            int r0 = rp*2, r1 = r0 + 1;
            float u0=0.f, v0=0.f, u1=0.f, v1=0.f;
            int t = 0;
#pragma unroll 8
            for (int n2 = 0; n2 < 128; ++n2) {
                float c = ct[t], s = st[t];
                float a = xs[r0][n2], b = xs[r1][n2];
                u0 += a*c; v0 += a*s;
                u1 += b*c; v1 += b*s;
                t = (t + k2) & 127;
            }
            int n1 = ch*32;
            U[n1+r0][k2] = u0; V[n1+r0][k2] = v0;
            U[n1+r1][k2] = u1; V[n1+r1][k2] = v1;
        }
    }
    __syncthreads();

    float* out = g_Xh + (size_t)bc * MODES_;
    for (int o = threadIdx.x; o < MODES_; o += 256) {
        int k1 = o / 20, k2 = o % 20;
        float cd = ct[k2], sd = st[k2];   // rotation by 2*pi*k2/128
        float acc = 0.f;
        int t = 0;                        // t = (k1*n1) mod 128
#pragma unroll 4
        for (int n1 = 0; n1 < 128; ++n1) {
            int tp = (t + k1) & 127;      // (k1*(n1+1)) mod 128
            float u = U[n1][k2], v = V[n1][k2];
            float ub = cd*u - sd*v;       // primed cos-projection
            float vb = sd*u + cd*v;       // primed sin-projection
            acc += ct[t]*u - st[t]*v - st[tp]*ub - ct[tp]*vb;
            t = tp;
        }
        out[o] = acc;
    }
}

// ---------------------------------------------------------------------------
// K2: compl_mul2d folded: Out = e(X, Wp) + e(Xneg, Wm),
// Wp = 0.5*(w + w_negk), Wm = 0.5*(w - w_negk). One block per (m1,m2) mode.
// ---------------------------------------------------------------------------
__global__ void __launch_bounds__(256) k_mul(const float* __restrict__ w1) {
    __shared__ float Xs[1024], Xn[1024], Wp[4096], Wm[4096];
    int m  = blockIdx.x;
    int m1 = m / 20, m2 = m % 20;
    int mn = ((20 - m1) % 20) * 20 + ((20 - m2) % 20);

    for (int i = threadIdx.x; i < 1024; i += 256) {
        Xs[i] = g_Xh[(size_t)i * MODES_ + m];
        Xn[i] = g_Xh[(size_t)i * MODES_ + mn];
    }
    for (int i = threadIdx.x; i < 4096; i += 256) {
        float w  = w1[(size_t)i * MODES_ + m];
        float wn = w1[(size_t)i * MODES_ + mn];
        Wp[i] = 0.5f * (w + wn);
        Wm[i] = 0.5f * (w - wn);
    }
    __syncthreads();

    for (int p = threadIdx.x; p < 1024; p += 256) {
        int b = p >> 6, o = p & 63;
        const float* xb  = Xs + b*64;
        const float* xnb = Xn + b*64;
        float acc = 0.f;
#pragma unroll 8
        for (int i = 0; i < 64; ++i)
            acc += xb[i]*Wp[i*64 + o] + xnb[i]*Wm[i*64 + o];
        g_Z[(size_t)p * MODES_ + m] = acc;
    }
}

// ---------------------------------------------------------------------------
// K3: inverse transform (modes 20x20 -> spatial 128x128), scaled by 1/(H*W).
// Only the 73 W-columns that survive the final mask (+blur halo) are computed:
// n2 in [0,36] U [92,127]. One block per (b,o).
// ---------------------------------------------------------------------------
__global__ void __launch_bounds__(256) k_inv(void) {
    __shared__ float ct[128], st[128];
    __shared__ float Zs[400];
    __shared__ float G1[20*NC_], G2[20*NC_], P1[20*NC_], P2[20*NC_];

    int bo = blockIdx.x;
    fill_tabs(ct, st);
    for (int i = threadIdx.x; i < 400; i += 256)
        Zs[i] = g_Z[(size_t)bo * MODES_ + i];
    __syncthreads();

    // Stage 1: contract over m2 for each (m1, column j)
    for (int idx = threadIdx.x; idx < 20*NC_; idx += 256) {
        int m1 = idx % 20;
        int j  = idx / 20;
        int n2 = (j < 37) ? j : j + 55;
        const float* zr = Zs + m1*20;
        float g1 = 0.f, g2 = 0.f;
        int t = 0;                          // (n2*m2) mod 128
#pragma unroll
        for (int m2 = 0; m2 < 20; ++m2) {
            float z = zr[m2];
            g1 += z * ct[t];
            g2 += z * st[t];
            t = (t + n2) & 127;
        }
        float cb = ct[n2], sb = st[n2];     // rotation by 2*pi*n2/128
        G1[m1*NC_ + j] = g1;
        G2[m1*NC_ + j] = g2;
        P1[m1*NC_ + j] = cb*g1 - sb*g2;     // primed cos-projection
        P2[m1*NC_ + j] = sb*g1 + cb*g2;     // primed sin-projection
    }
    __syncthreads();

    const float inv = 1.0f / 16384.0f;
    float* out = g_buf0 + (size_t)bo * HW_;
    for (int idx = threadIdx.x; idx < 128*NC_; idx += 256) {
        int n1 = idx / NC_, j = idx % NC_;
        int n2 = (j < 37) ? j : j + 55;
        float acc = 0.f;
        int t = 0;                          // (n1*m1) mod 128
#pragma unroll
        for (int m1 = 0; m1 < 20; ++m1) {
            int tp = (t + n1) & 127;        // (n1*(m1+1)) mod 128
            acc += ct[t]*G1[m1*NC_+j] - st[t]*G2[m1*NC_+j]
                 - st[tp]*P1[m1*NC_+j] - ct[tp]*P2[m1*NC_+j];
            t = tp;
        }
        out[n1*128 + n2] = acc * inv;
    }
}

// ---------------------------------------------------------------------------
// K4: W-axis 9-tap Gaussian (edge clamp) + low-pass mask. Masked-out columns
// are written as 0, so they stay 0 through the remaining (H,B,C) blurs.
// ---------------------------------------------------------------------------
__global__ void __launch_bounds__(256) k_wblur(void) {
    __shared__ float rows[2][128];
    int tid = threadIdx.x;
    int r = tid >> 7, w = tid & 127;
    size_t row = (size_t)blockIdx.x * 2 + r;
    rows[r][w] = g_buf0[row * 128 + w];
    __syncthreads();

    float acc = 0.f;
    if (w <= 32 || w >= 96) {
        float gk[9]; gauss9(gk);
#pragma unroll
        for (int t = 0; t < 9; ++t) {
            int ww = w + t - 4;
            ww = ww < 0 ? 0 : (ww > 127 ? 127 : ww);
            acc += gk[t] * rows[r][ww];
        }
    }
    g_buf1[row * 128 + w] = acc;
}

// ---------------------------------------------------------------------------
// K5: H-axis blur. Block = one (b,c) plane chunk of 16 rows + halo in smem.
// ---------------------------------------------------------------------------
__global__ void __launch_bounds__(256) k_hblur(void) {
    __shared__ float tile[24][128];
    int bc = blockIdx.x >> 3;
    int h0 = (blockIdx.x & 7) * 16;
    const float* in = g_buf1 + (size_t)bc * HW_;
    for (int idx = threadIdx.x; idx < 24*128; idx += 256) {
        int r = idx >> 7, w = idx & 127;
        int h = h0 + r - 4;
        h = h < 0 ? 0 : (h > 127 ? 127 : h);
        tile[r][w] = in[h*128 + w];
    }
    __syncthreads();

    float gk[9]; gauss9(gk);
    float* outp = g_buf0 + (size_t)bc * HW_;
    for (int idx = threadIdx.x; idx < 16*128; idx += 256) {
        int r = idx >> 7, w = idx & 127;
        float acc = 0.f;
#pragma unroll
        for (int t = 0; t < 9; ++t) acc += gk[t] * tile[r + t][w];
        outp[(h0 + r)*128 + w] = acc;
    }
}

// ---------------------------------------------------------------------------
// K6: B-axis blur (B=16). Each thread owns one (c,h,w) and the full B-line.
// ---------------------------------------------------------------------------
__global__ void __launch_bounds__(256) k_bblur(void) {
    size_t p = (size_t)blockIdx.x * 256 + threadIdx.x;   // over CO_*HW_ = 1048576
    float v[16];
#pragma unroll
    for (int b = 0; b < 16; ++b)
        v[b] = g_buf0[(size_t)b * ((size_t)CO_*HW_) + p];
    float gk[9]; gauss9(gk);
#pragma unroll
    for (int b = 0; b < 16; ++b) {
        float acc = 0.f;
#pragma unroll
        for (int t = 0; t < 9; ++t) {
            int bb = b + t - 4;
            bb = bb < 0 ? 0 : (bb > 15 ? 15 : bb);
            acc += gk[t] * v[bb];
        }
        g_buf1[(size_t)b * ((size_t)CO_*HW_) + p] = acc;
    }
}

// ---------------------------------------------------------------------------
// K7: C-axis blur (C=64) via sliding window, writes final output.
// ---------------------------------------------------------------------------
__global__ void __launch_bounds__(256) k_cblur(float* __restrict__ out) {
    int idx = blockIdx.x * 256 + threadIdx.x;            // over B_*HW_ = 262144
    int b  = idx >> 14;
    int hw = idx & 16383;
    const float* in = g_buf1 + (size_t)b * ((size_t)CO_*HW_) + hw;
    float* op       = out    + (size_t)b * ((size_t)CO_*HW_) + hw;

    float gk[9]; gauss9(gk);
    float win[9];
#pragma unroll
    for (int t = 0; t < 9; ++t) {
        int c = t - 4; c = c < 0 ? 0 : c;
        win[t] = in[(size_t)c * HW_];
    }
    for (int c = 0; c < 64; ++c) {
        float acc = 0.f;
#pragma unroll
        for (int t = 0; t < 9; ++t) acc += gk[t] * win[t];
        op[(size_t)c * HW_] = acc;
#pragma unroll
        for (int t = 0; t < 8; ++t) win[t] = win[t+1];
        int cn = c + 5; cn = cn > 63 ? 63 : cn;
        win[8] = in[(size_t)cn * HW_];
    }
}

extern "C" void kernel_launch(void* const* d_in, const int* in_sizes, int n_in,
                              void* d_out, int out_size) {
    (void)in_sizes; (void)n_in; (void)out_size;
    const float* x  = (const float*)d_in[0];
    const float* w1 = (const float*)d_in[1];
    float* out = (float*)d_out;

    k_fwd  <<<BC_,        256>>>(x);     // x -> Xh[1024,20,20]
    k_mul  <<<MODES_,     256>>>(w1);    // Xh,w1 -> Z[1024,20,20]
    k_inv  <<<BO_,        256>>>();      // Z -> buf0 (73 W-cols valid)
    k_wblur<<<BO_*N_/2,   256>>>();      // buf0 -> buf1 (W blur + mask)
    k_hblur<<<BO_*8,      256>>>();      // buf1 -> buf0 (H blur)
    k_bblur<<<CO_*HW_/256,256>>>();      // buf0 -> buf1 (B blur)
    k_cblur<<<B_*HW_/256, 256>>>(out);   // buf1 -> out  (C blur)
}

// round 3
// speedup vs baseline: 1.1475x; 1.1408x over previous
#include <cuda_runtime.h>
#include <cstddef>

#define B_   16
#define CO_  64
#define N_   128
#define HW_  16384
#define MODES_ 400
#define BC_  1024
#define BO_  1024
#define NC_  73          // computed W-cols: 0..36, 92..127
#define NK_  65          // kept W-cols: 0..32, 96..127
#define PS_  (N_*NK_)    // 8320 compact plane

__device__ float g_Xh[BC_*MODES_];
__device__ float g_Z [BO_*MODES_];
__device__ float g_buf0[(size_t)BO_*HW_];
__device__ float g_buf1[(size_t)BO_*HW_];

__constant__ float GK[9] = {
    1.3383062e-04f, 4.4318606e-03f, 5.3991128e-02f, 2.4197145e-01f,
    3.9894348e-01f, 2.4197145e-01f, 5.3991128e-02f, 4.4318606e-03f,
    1.3383062e-04f
};

__device__ __forceinline__ void fill_tabs(float* ct, float* st) {
    const float w = 6.283185307179586f / 128.0f;
    for (int t = threadIdx.x; t < 128; t += blockDim.x) {
        float s, c;
        sincosf(w * (float)t, &s, &c);
        ct[t] = c; st[t] = s;
    }
}

// K1: truncated forward DHT: x[bc,128,128] -> Xh[bc,20,20]
__global__ void __launch_bounds__(256) k_fwd(const float* __restrict__ x) {
    __shared__ float ct[128], st[128];
    __shared__ float xs[32][129];
    __shared__ float U[128][20], V[128][20];

    int bc = blockIdx.x;
    const float* xp = x + (size_t)bc * HW_;
    fill_tabs(ct, st);

    for (int ch = 0; ch < 4; ++ch) {
        __syncthreads();
        for (int idx = threadIdx.x; idx < 32*128; idx += 256) {
            int r = idx >> 7, n2 = idx & 127;
            xs[r][n2] = xp[(ch*32 + r)*128 + n2];
        }
        __syncthreads();
        for (int task = threadIdx.x; task < 320; task += 256) {
            int k2 = task % 20;
            int rp = task / 20;
            int r0 = rp*2, r1 = r0 + 1;
            float u0=0.f, v0=0.f, u1=0.f, v1=0.f;
            int t = 0;
#pragma unroll 8
            for (int n2 = 0; n2 < 128; ++n2) {
                float c = ct[t], s = st[t];
                float a = xs[r0][n2], b = xs[r1][n2];
                u0 += a*c; v0 += a*s;
                u1 += b*c; v1 += b*s;
                t = (t + k2) & 127;
            }
            int n1 = ch*32;
            U[n1+r0][k2] = u0; V[n1+r0][k2] = v0;
            U[n1+r1][k2] = u1; V[n1+r1][k2] = v1;
        }
    }
    __syncthreads();

    float* out = g_Xh + (size_t)bc * MODES_;
    for (int o = threadIdx.x; o < MODES_; o += 256) {
        int k1 = o / 20, k2 = o % 20;
        float cd = ct[k2], sd = st[k2];
        float acc = 0.f;
        int t = 0;
#pragma unroll 4
        for (int n1 = 0; n1 < 128; ++n1) {
            int tp = (t + k1) & 127;
            float u = U[n1][k2], v = V[n1][k2];
            float ub = cd*u - sd*v;
            float vb = sd*u + cd*v;
            acc += ct[t]*u - st[t]*v - st[tp]*ub - ct[tp]*vb;
            t = tp;
        }
        out[o] = acc;
    }
}

// K2: folded compl_mul2d: Z = e(X,Wp) + e(Xneg,Wm)
__global__ void __launch_bounds__(256) k_mul(const float* __restrict__ w1) {
    __shared__ float Xs[1024], Xn[1024], Wp[4096], Wm[4096];
    int m  = blockIdx.x;
    int m1 = m / 20, m2 = m % 20;
    int mn = ((20 - m1) % 20) * 20 + ((20 - m2) % 20);

    for (int i = threadIdx.x; i < 1024; i += 256) {
        Xs[i] = g_Xh[(size_t)i * MODES_ + m];
        Xn[i] = g_Xh[(size_t)i * MODES_ + mn];
    }
    for (int i = threadIdx.x; i < 4096; i += 256) {
        float w  = w1[(size_t)i * MODES_ + m];
        float wn = w1[(size_t)i * MODES_ + mn];
        Wp[i] = 0.5f * (w + wn);
        Wm[i] = 0.5f * (w - wn);
    }
    __syncthreads();

    for (int p = threadIdx.x; p < 1024; p += 256) {
        int b = p >> 6, o = p & 63;
        const float* xb  = Xs + b*64;
        const float* xnb = Xn + b*64;
        float acc = 0.f;
#pragma unroll 8
        for (int i = 0; i < 64; ++i)
            acc += xb[i]*Wp[i*64 + o] + xnb[i]*Wm[i*64 + o];
        g_Z[(size_t)p * MODES_ + m] = acc;
    }
}

// K3: inverse transform (w/ 1/HW). Writes COMPACT plane [128][73] per (b,o).
__global__ void __launch_bounds__(256) k_inv(void) {
    __shared__ float ct[128], st[128];
    __shared__ float Zs[400];
    __shared__ float G1[20*NC_], G2[20*NC_], P1[20*NC_], P2[20*NC_];

    int bo = blockIdx.x;
    fill_tabs(ct, st);
    for (int i = threadIdx.x; i < 400; i += 256)
        Zs[i] = g_Z[(size_t)bo * MODES_ + i];
    __syncthreads();

    for (int idx = threadIdx.x; idx < 20*NC_; idx += 256) {
        int m1 = idx % 20;
        int j  = idx / 20;
        int n2 = (j < 37) ? j : j + 55;
        const float* zr = Zs + m1*20;
        float g1 = 0.f, g2 = 0.f;
        int t = 0;
#pragma unroll
        for (int m2 = 0; m2 < 20; ++m2) {
            float z = zr[m2];
            g1 += z * ct[t];
            g2 += z * st[t];
            t = (t + n2) & 127;
        }
        float cb = ct[n2], sb = st[n2];
        G1[m1*NC_ + j] = g1;
        G2[m1*NC_ + j] = g2;
        P1[m1*NC_ + j] = cb*g1 - sb*g2;
        P2[m1*NC_ + j] = sb*g1 + cb*g2;
    }
    __syncthreads();

    const float inv = 6.103515625e-05f;  // 1/16384
    float* out = g_buf0 + (size_t)bo * (N_*NC_);
    for (int idx = threadIdx.x; idx < 128*NC_; idx += 256) {
        int n1 = idx / NC_, j = idx % NC_;
        float acc = 0.f;
        int t = 0;
#pragma unroll
        for (int m1 = 0; m1 < 20; ++m1) {
            int tp = (t + n1) & 127;
            acc += ct[t]*G1[m1*NC_+j] - st[t]*G2[m1*NC_+j]
                 - st[tp]*P1[m1*NC_+j] - ct[tp]*P2[m1*NC_+j];
            t = tp;
        }
        out[n1*NC_ + j] = acc * inv;
    }
}

// K4: fused W-blur(+mask) and H-blur per plane. In: compact73, out: compact65.
__global__ void __launch_bounds__(256) k_wh(void) {
    __shared__ float plane[N_*NC_];       // 9344 floats
    int tid = threadIdx.x;
    int bo  = blockIdx.x;
    const float* in = g_buf0 + (size_t)bo * (N_*NC_);
    for (int idx = tid; idx < N_*NC_; idx += 256) plane[idx] = in[idx];
    __syncthreads();

    // W-blur: thread = (row, half). Results staged in registers, then
    // written back IN PLACE (65-wide rows reuse the same smem).
    int row  = tid >> 1, half = tid & 1;
    int jbeg = half ? 33 : 0;
    int jcnt = half ? 32 : 33;
    float acc[33];
    const float* pr = plane + row * NC_;
    for (int q = 0; q < jcnt; ++q) {
        int j = jbeg + q;
        int w = (j < 33) ? j : j + 63;
        float a = 0.f;
#pragma unroll
        for (int t = 0; t < 9; ++t) {
            int ww = w + t - 4;
            ww = ww < 0 ? 0 : (ww > 127 ? 127 : ww);
            int p = ww < 37 ? ww : ww - 55;
            a += GK[t] * pr[p];
        }
        acc[q] = a;
    }
    __syncthreads();
    for (int q = 0; q < jcnt; ++q)
        plane[row * NK_ + jbeg + q] = acc[q];
    __syncthreads();

    // H-blur over 65-wide rows, write compact plane to g_buf1
    float* out = g_buf1 + (size_t)bo * PS_;
    for (int idx = tid; idx < PS_; idx += 256) {
        int r = idx / NK_, j = idx % NK_;
        float a = 0.f;
#pragma unroll
        for (int t = 0; t < 9; ++t) {
            int rr = r + t - 4;
            rr = rr < 0 ? 0 : (rr > 127 ? 127 : rr);
            a += GK[t] * plane[rr * NK_ + j];
        }
        out[idx] = a;
    }
}

// K5: B-axis blur on compact planes. g_buf1 -> g_buf0.
__global__ void __launch_bounds__(256) k_bblur(void) {
    size_t p = (size_t)blockIdx.x * 256 + threadIdx.x;   // over CO_*PS_
    float v[16];
#pragma unroll
    for (int b = 0; b < 16; ++b)
        v[b] = g_buf1[(size_t)b * ((size_t)CO_*PS_) + p];
#pragma unroll
    for (int b = 0; b < 16; ++b) {
        float a = 0.f;
#pragma unroll
        for (int t = 0; t < 9; ++t) {
            int bb = b + t - 4;
            bb = bb < 0 ? 0 : (bb > 15 ? 15 : bb);
            a += GK[t] * v[bb];
        }
        g_buf0[(size_t)b * ((size_t)CO_*PS_) + p] = a;
    }
}

// K6: zero the 63 masked output columns (w=33..95; w=96 re-written by k_cblur)
__global__ void __launch_bounds__(256) k_zero(float* __restrict__ out) {
    int idx = blockIdx.x * 256 + threadIdx.x;   // 131072 rows x 64 lanes
    int row = idx >> 6, lane = idx & 63;
    out[(size_t)row * 128 + 33 + lane] = 0.f;
}

// K7: C-axis blur (sliding window), expand compact -> full output layout.
__global__ void __launch_bounds__(256) k_cblur(float* __restrict__ out) {
    int idx = blockIdx.x * 256 + threadIdx.x;   // over B_*PS_ = 133120
    int b   = idx / PS_;
    int pos = idx % PS_;
    int r = pos / NK_, j = pos % NK_;
    int w = (j < 33) ? j : j + 63;

    const float* in = g_buf0 + (size_t)b * ((size_t)CO_*PS_) + pos;
    float* op = out + (size_t)b * ((size_t)CO_*HW_) + r*128 + w;

    float win[9];
#pragma unroll
    for (int t = 0; t < 9; ++t) {
        int c = t - 4; c = c < 0 ? 0 : c;
        win[t] = in[(size_t)c * PS_];
    }
    for (int c = 0; c < 64; ++c) {
        float a = 0.f;
#pragma unroll
        for (int t = 0; t < 9; ++t) a += GK[t] * win[t];
        op[(size_t)c * HW_] = a;
#pragma unroll
        for (int t = 0; t < 8; ++t) win[t] = win[t+1];
        int cn = c + 5; cn = cn > 63 ? 63 : cn;
        win[8] = in[(size_t)cn * PS_];
    }
}

extern "C" void kernel_launch(void* const* d_in, const int* in_sizes, int n_in,
                              void* d_out, int out_size) {
    (void)in_sizes; (void)n_in; (void)out_size;
    const float* x  = (const float*)d_in[0];
    const float* w1 = (const float*)d_in[1];
    float* out = (float*)d_out;

    k_fwd  <<<BC_, 256>>>(x);              // x -> Xh
    k_mul  <<<MODES_, 256>>>(w1);          // Xh,w1 -> Z
    k_inv  <<<BO_, 256>>>();               // Z -> g_buf0 (compact 73)
    k_wh   <<<BO_, 256>>>();               // W+mask+H -> g_buf1 (compact 65)
    k_bblur<<<(CO_*PS_)/256, 256>>>();     // g_buf1 -> g_buf0
    k_zero <<<(B_*CO_*N_*64)/256, 256>>>(out);
    k_cblur<<<(B_*PS_)/256, 256>>>(out);   // g_buf0 -> out
}

// round 4
// speedup vs baseline: 1.4021x; 1.2219x over previous
#include <cuda_runtime.h>
#include <cstddef>

#define B_   16
#define CO_  64
#define N_   128
#define HW_  16384
#define MODES_ 400
#define BC_  1024
#define BO_  1024
#define NC_  73          // computed W-cols: 0..36, 92..127
#define NK_  65          // kept W-cols: 0..32, 96..127
#define PS_  (N_*NK_)    // 8320
#define CPS_ (N_*NC_)    // 9344

__device__ float g_Xh[BC_*MODES_];
__device__ float g_Z [BO_*MODES_];
__device__ float g_buf0[(size_t)BO_*HW_];
__device__ float g_buf1[(size_t)BO_*HW_];

__constant__ float GK[9] = {
    1.3383062e-04f, 4.4318606e-03f, 5.3991128e-02f, 2.4197145e-01f,
    3.9894348e-01f, 2.4197145e-01f, 5.3991128e-02f, 4.4318606e-03f,
    1.3383062e-04f
};

__device__ __forceinline__ void fill_tabs(float* ct, float* st) {
    const float w = 6.283185307179586f / 128.0f;
    for (int t = threadIdx.x; t < 128; t += blockDim.x) {
        float s, c;
        sincosf(w * (float)t, &s, &c);
        ct[t] = c; st[t] = s;
    }
}

// ---------------------------------------------------------------------------
// K1: forward truncated DHT with parity-folded stage1 and E+parity stage2.
// ---------------------------------------------------------------------------
__global__ void __launch_bounds__(256) k_fwd(const float* __restrict__ x) {
    __shared__ float ct[128], st[128];
    __shared__ float xp[32][64], xm[32][64];
    __shared__ float U[128][20], V[128][20];
    float* F1 = &xp[0][0];   // [64][20] overlays xp after chunks done
    float* F2 = &xm[0][0];

    int tid = threadIdx.x;
    int bc  = blockIdx.x;
    const float* xb = x + (size_t)bc * HW_;
    fill_tabs(ct, st);

    for (int ch = 0; ch < 4; ++ch) {
        __syncthreads();
        for (int idx = tid; idx < 2048; idx += 256) {
            int r = idx >> 6, q = idx & 63;
            const float* row = xb + (ch*32 + r) * 128;
            if (q == 0) { xp[r][0] = row[0]; xm[r][0] = row[64]; }
            else {
                float a = row[q], b = row[128 - q];
                xp[r][q] = a + b; xm[r][q] = a - b;
            }
        }
        __syncthreads();
        for (int task = tid; task < 320; task += 256) {
            int k2 = task % 20, rp = task / 20;
            int r0 = rp*2, r1 = r0 + 1;
            float sgn = (k2 & 1) ? -1.f : 1.f;
            float u0 = xp[r0][0] + sgn * xm[r0][0];
            float u1 = xp[r1][0] + sgn * xm[r1][0];
            float v0 = 0.f, v1 = 0.f;
            int t0 = k2;
#pragma unroll 7
            for (int q = 1; q < 64; ++q) {
                float c = ct[t0], s = st[t0];
                u0 += xp[r0][q]*c; v0 += xm[r0][q]*s;
                u1 += xp[r1][q]*c; v1 += xm[r1][q]*s;
                t0 = (t0 + k2) & 127;
            }
            int n1 = ch*32;
            U[n1+r0][k2] = u0; V[n1+r0][k2] = v0;
            U[n1+r1][k2] = u1; V[n1+r1][k2] = v1;
        }
    }
    __syncthreads();

    // F build (E-fold + parity). F1[0][k2]=E1[0], F2[0][k2]=E1[64].
    for (int idx = tid; idx < 1280; idx += 256) {
        int n = idx / 20, k2 = idx % 20;
        float cd = ct[k2], sd = st[k2];
        if (n == 0) {
            F1[k2]      = U[0][k2]  - (sd*U[127][k2] + cd*V[127][k2]);
            F2[k2]      = U[64][k2] - (sd*U[63][k2]  + cd*V[63][k2]);
        } else {
            int nm = n - 1, nn = 128 - n, nnm = 127 - n;
            float e1a = U[n][k2]  - (sd*U[nm][k2]  + cd*V[nm][k2]);
            float e2a = V[n][k2]  + (cd*U[nm][k2]  - sd*V[nm][k2]);
            float e1b = U[nn][k2] - (sd*U[nnm][k2] + cd*V[nnm][k2]);
            float e2b = V[nn][k2] + (cd*U[nnm][k2] - sd*V[nnm][k2]);
            F1[n*20 + k2] = e1a + e1b;
            F2[n*20 + k2] = e2a - e2b;
        }
    }
    __syncthreads();

    float* out = g_Xh + (size_t)bc * MODES_;
    for (int o = tid; o < 400; o += 256) {
        int k1 = o / 20, k2 = o % 20;
        float acc = F1[k2] + ((k1 & 1) ? -F2[k2] : F2[k2]);
        int t = k1;
#pragma unroll 7
        for (int n = 1; n < 64; ++n) {
            acc += ct[t]*F1[n*20 + k2] - st[t]*F2[n*20 + k2];
            t = (t + k1) & 127;
        }
        out[o] = acc;
    }
}

// ---------------------------------------------------------------------------
// K2: folded compl_mul2d
// ---------------------------------------------------------------------------
__global__ void __launch_bounds__(256) k_mul(const float* __restrict__ w1) {
    __shared__ float Xs[1024], Xn[1024], Wp[4096], Wm[4096];
    int m  = blockIdx.x;
    int m1 = m / 20, m2 = m % 20;
    int mn = ((20 - m1) % 20) * 20 + ((20 - m2) % 20);

    for (int i = threadIdx.x; i < 1024; i += 256) {
        Xs[i] = g_Xh[(size_t)i * MODES_ + m];
        Xn[i] = g_Xh[(size_t)i * MODES_ + mn];
    }
    for (int i = threadIdx.x; i < 4096; i += 256) {
        float w  = w1[(size_t)i * MODES_ + m];
        float wn = w1[(size_t)i * MODES_ + mn];
        Wp[i] = 0.5f * (w + wn);
        Wm[i] = 0.5f * (w - wn);
    }
    __syncthreads();

    for (int p = threadIdx.x; p < 1024; p += 256) {
        int b = p >> 6, o = p & 63;
        const float* xb  = Xs + b*64;
        const float* xnb = Xn + b*64;
        float acc = 0.f;
#pragma unroll 8
        for (int i = 0; i < 64; ++i)
            acc += xb[i]*Wp[i*64 + o] + xnb[i]*Wm[i*64 + o];
        g_Z[(size_t)p * MODES_ + m] = acc;
    }
}

// ---------------------------------------------------------------------------
// K3: inverse transform, E-fold + parity, register trig, column-major out.
// out plane: g_buf0[bo*CPS_ + j*128 + n1], j in 0..72.
// ---------------------------------------------------------------------------
__global__ void __launch_bounds__(256) k_inv(void) {
    __shared__ float ct[128], st[128], Zs[400];
    __shared__ float G1[20][73], G2[20][73], P1[20][73], P2[20][73];
    __shared__ float A[21][73], Bb[21][73];

    int tid = threadIdx.x;
    int bo  = blockIdx.x;
    fill_tabs(ct, st);
    for (int i = tid; i < 400; i += 256) Zs[i] = g_Z[(size_t)bo * MODES_ + i];
    __syncthreads();

    const float inv = 6.103515625e-05f;  // 1/16384 folded here
    for (int idx = tid; idx < 1460; idx += 256) {
        int m1 = idx / 73, j = idx - m1*73;
        int n2 = (j < 37) ? j : j + 55;
        const float* zr = Zs + m1*20;
        float g1 = 0.f, g2 = 0.f;
        int t = 0;
#pragma unroll
        for (int m2 = 0; m2 < 20; ++m2) {
            float z = zr[m2];
            g1 += z * ct[t]; g2 += z * st[t];
            t = (t + n2) & 127;
        }
        g1 *= inv; g2 *= inv;
        float cb = ct[n2], sb = st[n2];
        G1[m1][j] = g1; G2[m1][j] = g2;
        P1[m1][j] = cb*g1 - sb*g2;
        P2[m1][j] = sb*g1 + cb*g2;
    }
    __syncthreads();

    for (int idx = tid; idx < 1533; idx += 256) {
        int m = idx / 73, j = idx - m*73;
        float a = 0.f, b = 0.f;
        if (m < 20) { a = G1[m][j]; b = G2[m][j]; }
        if (m > 0)  { a -= P2[m-1][j]; b += P1[m-1][j]; }
        A[m][j] = a; Bb[m][j] = b;
    }
    __syncthreads();

    int n1p   = tid & 63;
    int chunk = tid >> 6;
    float cm[21], sm[21];
#pragma unroll
    for (int m = 0; m < 21; ++m) {
        int tt = (n1p * m) & 127;
        cm[m] = ct[tt]; sm[m] = st[tt];
    }
    float* outp = g_buf0 + (size_t)bo * CPS_;
    for (int j = chunk; j < 73; j += 4) {
        float sc = 0.f, ss = 0.f, s64 = 0.f;
#pragma unroll
        for (int m = 0; m < 21; ++m) {
            float a = A[m][j], b = Bb[m][j];
            sc += cm[m]*a; ss += sm[m]*b;
            s64 += (m & 1) ? -a : a;
        }
        outp[j*128 + n1p] = sc - ss;
        outp[j*128 + ((128 - n1p) & 127)] = sc + ss;
        if (n1p == 0) outp[j*128 + 64] = s64;
    }
}

// ---------------------------------------------------------------------------
// K4: fused W-blur(+mask) and H-blur. Column-major smem (stride 129).
// Out: g_buf1[bo*PS_ + r*65 + j]  (row-major compact).
// ---------------------------------------------------------------------------
__global__ void __launch_bounds__(256) k_wh(void) {
    __shared__ float pl[73*129];
    __shared__ int cmap[65*9];
    int tid = threadIdx.x;
    int bo  = blockIdx.x;
    const float* in = g_buf0 + (size_t)bo * CPS_;
    for (int idx = tid; idx < CPS_; idx += 256) {
        int j = idx >> 7, r = idx & 127;
        pl[j*129 + r] = in[idx];
    }
    for (int idx = tid; idx < 585; idx += 256) {
        int jj = idx / 9, t = idx - jj*9;
        int w  = (jj < 33) ? jj : jj + 63;
        int ww = w + t - 4;
        ww = ww < 0 ? 0 : (ww > 127 ? 127 : ww);
        int p = (ww < 37) ? ww : ww - 55;
        cmap[idx] = p * 129;
    }
    __syncthreads();

    float acc[33];
#pragma unroll
    for (int i = 0; i < 33; ++i) {
        int idx = tid + 256*i;
        if (idx < PS_) {
            int j = idx >> 7, r = idx & 127;
            const int* cmp = cmap + j*9;
            float a = 0.f;
#pragma unroll
            for (int t = 0; t < 9; ++t) a += GK[t] * pl[cmp[t] + r];
            acc[i] = a;
        }
    }
    __syncthreads();
#pragma unroll
    for (int i = 0; i < 33; ++i) {
        int idx = tid + 256*i;
        if (idx < PS_) {
            int j = idx >> 7, r = idx & 127;
            pl[j*129 + r] = acc[i];
        }
    }
    __syncthreads();

    float* out = g_buf1 + (size_t)bo * PS_;
    for (int idx = tid; idx < PS_; idx += 256) {
        int r = idx / 65, j = idx - r*65;
        float a = 0.f;
#pragma unroll
        for (int t = 0; t < 9; ++t) {
            int rr = r + t - 4;
            rr = rr < 0 ? 0 : (rr > 127 ? 127 : rr);
            a += GK[t] * pl[j*129 + rr];
        }
        out[idx] = a;
    }
}

// K5: B-axis blur (layout agnostic). g_buf1 -> g_buf0.
__global__ void __launch_bounds__(256) k_bblur(void) {
    size_t p = (size_t)blockIdx.x * 256 + threadIdx.x;   // over CO_*PS_
    float v[16];
#pragma unroll
    for (int b = 0; b < 16; ++b)
        v[b] = g_buf1[(size_t)b * ((size_t)CO_*PS_) + p];
#pragma unroll
    for (int b = 0; b < 16; ++b) {
        float a = 0.f;
#pragma unroll
        for (int t = 0; t < 9; ++t) {
            int bb = b + t - 4;
            bb = bb < 0 ? 0 : (bb > 15 ? 15 : bb);
            a += GK[t] * v[bb];
        }
        g_buf0[(size_t)b * ((size_t)CO_*PS_) + p] = a;
    }
}

// K6: zero masked output columns (w=33..96; w=96 rewritten by k_cblur after).
__global__ void __launch_bounds__(256) k_zero(float* __restrict__ out) {
    int idx = blockIdx.x * 256 + threadIdx.x;
    int row = idx >> 6, lane = idx & 63;
    out[(size_t)row * 128 + 33 + lane] = 0.f;
}

// K7: C-axis blur (sliding window), expand row-major compact -> full layout.
__global__ void __launch_bounds__(256) k_cblur(float* __restrict__ out) {
    int idx = blockIdx.x * 256 + threadIdx.x;   // over B_*PS_
    int b   = idx / PS_;
    int pos = idx - b * PS_;
    int r = pos / 65, j = pos - r*65;
    int w = (j < 33) ? j : j + 63;

    const float* in = g_buf0 + (size_t)b * ((size_t)CO_*PS_) + pos;
    float* op = out + (size_t)b * ((size_t)CO_*HW_) + r*128 + w;

    float win[9];
#pragma unroll
    for (int t = 0; t < 9; ++t) {
        int c = t - 4; c = c < 0 ? 0 : c;
        win[t] = in[(size_t)c * PS_];
    }
    for (int c = 0; c < 64; ++c) {
        float a = 0.f;
#pragma unroll
        for (int t = 0; t < 9; ++t) a += GK[t] * win[t];
        op[(size_t)c * HW_] = a;
#pragma unroll
        for (int t = 0; t < 8; ++t) win[t] = win[t+1];
        int cn = c + 5; cn = cn > 63 ? 63 : cn;
        win[8] = in[(size_t)cn * PS_];
    }
}

extern "C" void kernel_launch(void* const* d_in, const int* in_sizes, int n_in,
                              void* d_out, int out_size) {
    (void)in_sizes; (void)n_in; (void)out_size;
    const float* x  = (const float*)d_in[0];
    const float* w1 = (const float*)d_in[1];
    float* out = (float*)d_out;

    k_fwd  <<<BC_, 256>>>(x);
    k_mul  <<<MODES_, 256>>>(w1);
    k_inv  <<<BO_, 256>>>();
    k_wh   <<<BO_, 256>>>();
    k_bblur<<<(CO_*PS_)/256, 256>>>();
    k_zero <<<(B_*CO_*N_*64)/256, 256>>>(out);
    k_cblur<<<(B_*PS_ + 255)/256, 256>>>(out);
}

// round 5
// speedup vs baseline: 1.4097x; 1.0054x over previous
#include <cuda_runtime.h>
#include <cstddef>

#define B_   16
#define CO_  64
#define N_   128
#define HW_  16384
#define MODES_ 400
#define BC_  1024
#define BO_  1024
#define NC_  73
#define NK_  65
#define PS_  (N_*NK_)    // 8320
#define IW_SMEM 54896    // bytes of dynamic smem in k_invwh

__device__ float g_Xh[BC_*MODES_];
__device__ float g_Z [BO_*MODES_];
__device__ float g_buf1[(size_t)BO_*PS_];

__constant__ float GK[9] = {
    1.3383062e-04f, 4.4318606e-03f, 5.3991128e-02f, 2.4197145e-01f,
    3.9894348e-01f, 2.4197145e-01f, 5.3991128e-02f, 4.4318606e-03f,
    1.3383062e-04f
};

__device__ __forceinline__ void fill_tabs(float* ct, float* st) {
    const float w = 6.283185307179586f / 128.0f;
    for (int t = threadIdx.x; t < 128; t += blockDim.x) {
        float s, c;
        sincosf(w * (float)t, &s, &c);
        ct[t] = c; st[t] = s;
    }
}

// K1: forward truncated DHT (parity-folded stage1, E+parity stage2)
__global__ void __launch_bounds__(256) k_fwd(const float* __restrict__ x) {
    __shared__ float ct[128], st[128];
    __shared__ float xp[32][64], xm[32][64];
    __shared__ float U[128][20], V[128][20];
    float* F1 = &xp[0][0];
    float* F2 = &xm[0][0];

    int tid = threadIdx.x;
    int bc  = blockIdx.x;
    const float* xb = x + (size_t)bc * HW_;
    fill_tabs(ct, st);

    for (int ch = 0; ch < 4; ++ch) {
        __syncthreads();
        for (int idx = tid; idx < 2048; idx += 256) {
            int r = idx >> 6, q = idx & 63;
            const float* row = xb + (ch*32 + r) * 128;
            if (q == 0) { xp[r][0] = row[0]; xm[r][0] = row[64]; }
            else {
                float a = row[q], b = row[128 - q];
                xp[r][q] = a + b; xm[r][q] = a - b;
            }
        }
        __syncthreads();
        for (int task = tid; task < 320; task += 256) {
            int k2 = task % 20, rp = task / 20;
            int r0 = rp*2, r1 = r0 + 1;
            float sgn = (k2 & 1) ? -1.f : 1.f;
            float u0 = xp[r0][0] + sgn * xm[r0][0];
            float u1 = xp[r1][0] + sgn * xm[r1][0];
            float v0 = 0.f, v1 = 0.f;
            int t0 = k2;
#pragma unroll 7
            for (int q = 1; q < 64; ++q) {
                float c = ct[t0], s = st[t0];
                u0 += xp[r0][q]*c; v0 += xm[r0][q]*s;
                u1 += xp[r1][q]*c; v1 += xm[r1][q]*s;
                t0 = (t0 + k2) & 127;
            }
            int n1 = ch*32;
            U[n1+r0][k2] = u0; V[n1+r0][k2] = v0;
            U[n1+r1][k2] = u1; V[n1+r1][k2] = v1;
        }
    }
    __syncthreads();

    for (int idx = tid; idx < 1280; idx += 256) {
        int n = idx / 20, k2 = idx % 20;
        float cd = ct[k2], sd = st[k2];
        if (n == 0) {
            F1[k2] = U[0][k2]  - (sd*U[127][k2] + cd*V[127][k2]);
            F2[k2] = U[64][k2] - (sd*U[63][k2]  + cd*V[63][k2]);
        } else {
            int nm = n - 1, nn = 128 - n, nnm = 127 - n;
            float e1a = U[n][k2]  - (sd*U[nm][k2]  + cd*V[nm][k2]);
            float e2a = V[n][k2]  + (cd*U[nm][k2]  - sd*V[nm][k2]);
            float e1b = U[nn][k2] - (sd*U[nnm][k2] + cd*V[nnm][k2]);
            float e2b = V[nn][k2] + (cd*U[nnm][k2] - sd*V[nnm][k2]);
            F1[n*20 + k2] = e1a + e1b;
            F2[n*20 + k2] = e2a - e2b;
        }
    }
    __syncthreads();

    float* out = g_Xh + (size_t)bc * MODES_;
    for (int o = tid; o < 400; o += 256) {
        int k1 = o / 20, k2 = o % 20;
        float acc = F1[k2] + ((k1 & 1) ? -F2[k2] : F2[k2]);
        int t = k1;
#pragma unroll 7
        for (int n = 1; n < 64; ++n) {
            acc += ct[t]*F1[n*20 + k2] - st[t]*F2[n*20 + k2];
            t = (t + k1) & 127;
        }
        out[o] = acc;
    }
}

// K2: folded compl_mul2d
__global__ void __launch_bounds__(256) k_mul(const float* __restrict__ w1) {
    __shared__ float Xs[1024], Xn[1024], Wp[4096], Wm[4096];
    int m  = blockIdx.x;
    int m1 = m / 20, m2 = m % 20;
    int mn = ((20 - m1) % 20) * 20 + ((20 - m2) % 20);

    for (int i = threadIdx.x; i < 1024; i += 256) {
        Xs[i] = g_Xh[(size_t)i * MODES_ + m];
        Xn[i] = g_Xh[(size_t)i * MODES_ + mn];
    }
    for (int i = threadIdx.x; i < 4096; i += 256) {
        float w  = w1[(size_t)i * MODES_ + m];
        float wn = w1[(size_t)i * MODES_ + mn];
        Wp[i] = 0.5f * (w + wn);
        Wm[i] = 0.5f * (w - wn);
    }
    __syncthreads();

    for (int p = threadIdx.x; p < 1024; p += 256) {
        int b = p >> 6, o = p & 63;
        const float* xb  = Xs + b*64;
        const float* xnb = Xn + b*64;
        float acc = 0.f;
#pragma unroll 8
        for (int i = 0; i < 64; ++i)
            acc += xb[i]*Wp[i*64 + o] + xnb[i]*Wm[i*64 + o];
        g_Z[(size_t)p * MODES_ + m] = acc;
    }
}

// K3: FUSED inverse transform + W-blur(+mask) + H-blur. One block per (b,o).
// Dynamic smem layout (floats):
//  ct[128] st[128] Zs[400] A[1533] Bb[1533] pl[9417] cmap(int)[585]
//  G1..P2 (4x1460) overlay pl (dead before stage2 writes pl).
__global__ void __launch_bounds__(256) k_invwh(void) {
    extern __shared__ float sm[];
    float* ct = sm;
    float* st = sm + 128;
    float* Zs = sm + 256;
    float* A  = sm + 656;
    float* Bb = A + 1533;
    float* pl = Bb + 1533;          // stride 129, 73 cols
    float* G1 = pl;
    float* G2 = pl + 1460;
    float* P1 = pl + 2920;
    float* P2 = pl + 4380;
    int*  cmap = (int*)(sm + 13139);

    int tid = threadIdx.x;
    int bo  = blockIdx.x;
    fill_tabs(ct, st);
    for (int i = tid; i < 400; i += 256) Zs[i] = g_Z[(size_t)bo * MODES_ + i];
    for (int idx = tid; idx < 585; idx += 256) {
        int jj = idx / 9, t = idx - jj*9;
        int w  = (jj < 33) ? jj : jj + 63;
        int ww = w + t - 4;
        ww = ww < 0 ? 0 : (ww > 127 ? 127 : ww);
        int p = (ww < 37) ? ww : ww - 55;
        cmap[idx] = p * 129;
    }
    __syncthreads();

    // phase A: cos/sin projections over m2, rotated versions
    const float inv = 6.103515625e-05f;
    for (int idx = tid; idx < 1460; idx += 256) {
        int m1 = idx / 73, j = idx - m1*73;
        int n2 = (j < 37) ? j : j + 55;
        const float* zr = Zs + m1*20;
        float g1 = 0.f, g2 = 0.f;
        int t = 0;
#pragma unroll
        for (int m2 = 0; m2 < 20; ++m2) {
            float z = zr[m2];
            g1 += z * ct[t]; g2 += z * st[t];
            t = (t + n2) & 127;
        }
        g1 *= inv; g2 *= inv;
        float cb = ct[n2], sb = st[n2];
        G1[m1*73+j] = g1; G2[m1*73+j] = g2;
        P1[m1*73+j] = cb*g1 - sb*g2;
        P2[m1*73+j] = sb*g1 + cb*g2;
    }
    __syncthreads();

    // E-fold into A,Bb
    for (int idx = tid; idx < 1533; idx += 256) {
        int m = idx / 73, j = idx - m*73;
        float a = 0.f, b = 0.f;
        if (m < 20) { a = G1[m*73+j]; b = G2[m*73+j]; }
        if (m > 0)  { a -= P2[(m-1)*73+j]; b += P1[(m-1)*73+j]; }
        A[idx] = a; Bb[idx] = b;
    }
    __syncthreads();

    // stage2: register trig, parity-paired outputs -> pl (overlays G..P)
    {
        int n1p   = tid & 63;
        int chunk = tid >> 6;
        float cm[21], smv[21];
#pragma unroll
        for (int m = 0; m < 21; ++m) {
            int tt = (n1p * m) & 127;
            cm[m] = ct[tt]; smv[m] = st[tt];
        }
        for (int j = chunk; j < 73; j += 4) {
            float sc = 0.f, ss = 0.f, s64 = 0.f;
#pragma unroll
            for (int m = 0; m < 21; ++m) {
                float a = A[m*73+j], b = Bb[m*73+j];
                sc += cm[m]*a; ss += smv[m]*b;
                s64 += (m & 1) ? -a : a;
            }
            pl[j*129 + n1p] = sc - ss;
            pl[j*129 + ((128 - n1p) & 127)] = sc + ss;
            if (n1p == 0) pl[j*129 + 64] = s64;
        }
    }
    __syncthreads();

    // W-blur (+mask) via cmap, register-staged, write back in place (65 cols)
    float acc[33];
#pragma unroll
    for (int i = 0; i < 33; ++i) {
        int idx = tid + 256*i;
        if (idx < PS_) {
            int j = idx >> 7, r = idx & 127;
            const int* cmp = cmap + j*9;
            float a = 0.f;
#pragma unroll
            for (int t = 0; t < 9; ++t) a += GK[t] * pl[cmp[t] + r];
            acc[i] = a;
        }
    }
    __syncthreads();
#pragma unroll
    for (int i = 0; i < 33; ++i) {
        int idx = tid + 256*i;
        if (idx < PS_) {
            int j = idx >> 7, r = idx & 127;
            pl[j*129 + r] = acc[i];
        }
    }
    __syncthreads();

    // H-blur -> row-major compact plane in g_buf1
    float* out = g_buf1 + (size_t)bo * PS_;
    for (int idx = tid; idx < PS_; idx += 256) {
        int r = idx / 65, j = idx - r*65;
        float a = 0.f;
#pragma unroll
        for (int t = 0; t < 9; ++t) {
            int rr = r + t - 4;
            rr = rr < 0 ? 0 : (rr > 127 ? 127 : rr);
            a += GK[t] * pl[j*129 + rr];
        }
        out[idx] = a;
    }
}

// K4: zero masked output columns (w=33..96; w=96 later rewritten by k_bc)
__global__ void __launch_bounds__(256) k_zero(float* __restrict__ out) {
    int idx = blockIdx.x * 256 + threadIdx.x;
    int row = idx >> 6, lane = idx & 63;
    out[(size_t)row * 128 + 33 + lane] = 0.f;
}

// K5: FUSED B-blur + C-blur over a [16][64][8-pos] tile; expands to output.
// smem stride 520 -> conflict-free for both blur directions.
__global__ void __launch_bounds__(256) k_bc(float* __restrict__ out) {
    __shared__ float t[16*520];
    __shared__ int rr8[8], ww8[8];
    int tid = threadIdx.x;
    int p0  = blockIdx.x * 8;

    if (tid < 8) {
        int pos = p0 + tid;
        int r = pos / 65, j = pos - r*65;
        rr8[tid] = r;
        ww8[tid] = (j < 33) ? j : j + 63;
    }
    // load tile (coalesced 32B rows per (b,c))
    for (int idx = tid; idx < 8192; idx += 256) {
        int b = idx >> 9, rem = idx & 511;        // rem = c*8+p
        int c = rem >> 3, p = rem & 7;
        t[b*520 + rem] = g_buf1[(size_t)b*(CO_*PS_) + (size_t)c*PS_ + p0 + p];
    }
    __syncthreads();

    // B-blur: thread owns (c,p) columns exclusively -> in-place safe
    for (int task = tid; task < 512; task += 256) {
        float v[16], o[16];
#pragma unroll
        for (int b = 0; b < 16; ++b) v[b] = t[b*520 + task];
#pragma unroll
        for (int b = 0; b < 16; ++b) {
            float a = 0.f;
#pragma unroll
            for (int k = 0; k < 9; ++k) {
                int bb = b + k - 4;
                bb = bb < 0 ? 0 : (bb > 15 ? 15 : bb);
                a += GK[k] * v[bb];
            }
            o[b] = a;
        }
#pragma unroll
        for (int b = 0; b < 16; ++b) t[b*520 + task] = o[b];
    }
    __syncthreads();

    // C-blur: thread owns (b,p) line exclusively -> in-place safe
    if (tid < 128) {
        int b = tid >> 3, p = tid & 7;
        float* line = t + b*520 + p;              // stride 8 over c
        float win[9];
#pragma unroll
        for (int k = 0; k < 9; ++k) {
            int c = k - 4; c = c < 0 ? 0 : c;
            win[k] = line[c*8];
        }
        float res[64];
        for (int c = 0; c < 64; ++c) {
            float a = 0.f;
#pragma unroll
            for (int k = 0; k < 9; ++k) a += GK[k] * win[k];
            res[c] = a;
#pragma unroll
            for (int k = 0; k < 8; ++k) win[k] = win[k+1];
            int cn = c + 5; cn = cn > 63 ? 63 : cn;
            win[8] = line[cn*8];
        }
        for (int c = 0; c < 64; ++c) line[c*8] = res[c];
    }
    __syncthreads();

    // store expanded (coalesced 32B rows per (b,c))
    for (int idx = tid; idx < 8192; idx += 256) {
        int b = idx >> 9, rem = idx & 511;
        int c = rem >> 3, p = rem & 7;
        out[(size_t)b*(CO_*HW_) + (size_t)c*HW_ + rr8[p]*128 + ww8[p]]
            = t[b*520 + rem];
    }
}

extern "C" void kernel_launch(void* const* d_in, const int* in_sizes, int n_in,
                              void* d_out, int out_size) {
    (void)in_sizes; (void)n_in; (void)out_size;
    const float* x  = (const float*)d_in[0];
    const float* w1 = (const float*)d_in[1];
    float* out = (float*)d_out;

    cudaFuncSetAttribute(k_invwh, cudaFuncAttributeMaxDynamicSharedMemorySize,
                         IW_SMEM);
    k_fwd  <<<BC_, 256>>>(x);
    k_mul  <<<MODES_, 256>>>(w1);
    k_invwh<<<BO_, 256, IW_SMEM>>>();
    k_zero <<<(B_*CO_*N_*64)/256, 256>>>(out);
    k_bc   <<<PS_/8, 256>>>(out);
}

// round 6
// speedup vs baseline: 2.0897x; 1.4824x over previous
#include <cuda_runtime.h>
#include <cstddef>

#define B_   16
#define CO_  64
#define N_   128
#define HW_  16384
#define MODES_ 400
#define BC_  1024
#define BO_  1024
#define NC_  73
#define NK_  65
#define PS_  (N_*NK_)      // 8320
#define FW_SMEM  98304     // k_fwd dynamic smem bytes (24576 floats)
#define IW_SMEM  54976     // k_invwh dynamic smem bytes (13744 floats)

__device__ float g_Xh[BC_*MODES_];
__device__ float g_Z [BO_*MODES_];
__device__ float g_buf1[(size_t)BO_*PS_];

__constant__ float GK[9] = {
    1.3383062e-04f, 4.4318606e-03f, 5.3991128e-02f, 2.4197145e-01f,
    3.9894348e-01f, 2.4197145e-01f, 5.3991128e-02f, 4.4318606e-03f,
    1.3383062e-04f
};

__device__ __forceinline__ void fill_tabs_n(float* ct, float* st, int nthr) {
    const float w = 6.283185307179586f / 128.0f;
    for (int t = threadIdx.x; t < 128; t += nthr) {
        float s, c;
        sincosf(w * (float)t, &s, &c);
        ct[t] = c; st[t] = s;
    }
}

// ---------------------------------------------------------------------------
// K1: forward truncated DHT. Stage1 as register-tiled GEMM:
//   U[128][20] = Xp[128][64] * CT[64][20],  V = Xm * ST
// (q=0 column of CT is 1, of ST is 0; the x[r][64] term is a sign fixup.)
// Then E-fold + parity stage2 -> Xh[bc][400].
// ---------------------------------------------------------------------------
__global__ void __launch_bounds__(320) k_fwd(const float* __restrict__ x) {
    extern __shared__ float sm[];
    float* ct = sm;             // 128
    float* st = sm + 128;       // 128
    float* CT = sm + 256;       // 64*20
    float* ST = CT + 1280;      // 64*20
    float* xp = ST + 1280;      // 128*65 (padded)
    float* xm = xp + 8320;      // 128*65
    float* U  = xm + 8320;      // 128*20
    float* V  = U + 2560;       // 128*20
    float* F1 = xp;             // overlay after GEMM ([64][20])
    float* F2 = xm;

    int tid = threadIdx.x;
    int bc  = blockIdx.x;
    const float* xb = x + (size_t)bc * HW_;

    fill_tabs_n(ct, st, 320);
    __syncthreads();

    for (int idx = tid; idx < 1280; idx += 320) {
        int q = idx / 20, k2 = idx - q*20;
        if (q == 0) { CT[idx] = 1.f; ST[idx] = 0.f; }
        else {
            int t = (q * k2) & 127;
            CT[idx] = ct[t]; ST[idx] = st[t];
        }
    }
    for (int idx = tid; idx < 8192; idx += 320) {
        int r = idx >> 6, q = idx & 63;
        const float* row = xb + r * 128;
        if (q == 0) { xp[r*65] = row[0]; xm[r*65] = row[64]; }
        else {
            float a = row[q], b = row[128 - q];
            xp[r*65 + q] = a + b; xm[r*65 + q] = a - b;
        }
    }
    __syncthreads();

    // GEMM: lane = ty (rows ty, ty+32, ty+64, ty+96), warp tx = col group
    {
        int ty = tid & 31, tx = tid >> 5;       // tx in 0..9
        int isU = (tx < 5);
        int c0  = (isU ? tx : tx - 5) * 4;
        const float* A  = isU ? xp : xm;
        const float* Bm = isU ? CT : ST;
        float acc[4][4];
#pragma unroll
        for (int i = 0; i < 4; ++i)
#pragma unroll
            for (int j = 0; j < 4; ++j) acc[i][j] = 0.f;

#pragma unroll 4
        for (int q = 0; q < 64; ++q) {
            float b0 = Bm[q*20 + c0];
            float b1 = Bm[q*20 + c0 + 1];
            float b2 = Bm[q*20 + c0 + 2];
            float b3 = Bm[q*20 + c0 + 3];
#pragma unroll
            for (int i = 0; i < 4; ++i) {
                float a = A[(ty + 32*i)*65 + q];
                acc[i][0] += a*b0; acc[i][1] += a*b1;
                acc[i][2] += a*b2; acc[i][3] += a*b3;
            }
        }
        float* O = isU ? U : V;
#pragma unroll
        for (int i = 0; i < 4; ++i) {
            float pm = isU ? xm[(ty + 32*i)*65] : 0.f;
#pragma unroll
            for (int j = 0; j < 4; ++j) {
                float v = acc[i][j];
                if (isU) v += ((c0 + j) & 1) ? -pm : pm;
                O[(ty + 32*i)*20 + c0 + j] = v;
            }
        }
    }
    __syncthreads();

    // F build (E-fold + parity)
    for (int idx = tid; idx < 1280; idx += 320) {
        int n = idx / 20, k2 = idx - n*20;
        float cd = ct[k2], sd = st[k2];
        if (n == 0) {
            F1[k2] = U[0*20+k2]  - (sd*U[127*20+k2] + cd*V[127*20+k2]);
            F2[k2] = U[64*20+k2] - (sd*U[63*20+k2]  + cd*V[63*20+k2]);
        } else {
            int nm = n - 1, nn = 128 - n, nnm = 127 - n;
            float e1a = U[n*20+k2]  - (sd*U[nm*20+k2]  + cd*V[nm*20+k2]);
            float e2a = V[n*20+k2]  + (cd*U[nm*20+k2]  - sd*V[nm*20+k2]);
            float e1b = U[nn*20+k2] - (sd*U[nnm*20+k2] + cd*V[nnm*20+k2]);
            float e2b = V[nn*20+k2] + (cd*U[nnm*20+k2] - sd*V[nnm*20+k2]);
            F1[n*20 + k2] = e1a + e1b;
            F2[n*20 + k2] = e2a - e2b;
        }
    }
    __syncthreads();

    float* out = g_Xh + (size_t)bc * MODES_;
    for (int o = tid; o < 400; o += 320) {
        int k1 = o / 20, k2 = o - k1*20;
        float acc = F1[k2] + ((k1 & 1) ? -F2[k2] : F2[k2]);
        int t = k1;
#pragma unroll 7
        for (int n = 1; n < 64; ++n) {
            acc += ct[t]*F1[n*20 + k2] - st[t]*F2[n*20 + k2];
            t = (t + k1) & 127;
        }
        out[o] = acc;
    }
}

// ---------------------------------------------------------------------------
// K2: folded compl_mul2d
// ---------------------------------------------------------------------------
__global__ void __launch_bounds__(256) k_mul(const float* __restrict__ w1) {
    __shared__ float Xs[1024], Xn[1024], Wp[4096], Wm[4096];
    int m  = blockIdx.x;
    int m1 = m / 20, m2 = m % 20;
    int mn = ((20 - m1) % 20) * 20 + ((20 - m2) % 20);

    for (int i = threadIdx.x; i < 1024; i += 256) {
        Xs[i] = g_Xh[(size_t)i * MODES_ + m];
        Xn[i] = g_Xh[(size_t)i * MODES_ + mn];
    }
    for (int i = threadIdx.x; i < 4096; i += 256) {
        float w  = w1[(size_t)i * MODES_ + m];
        float wn = w1[(size_t)i * MODES_ + mn];
        Wp[i] = 0.5f * (w + wn);
        Wm[i] = 0.5f * (w - wn);
    }
    __syncthreads();

    for (int p = threadIdx.x; p < 1024; p += 256) {
        int b = p >> 6, o = p & 63;
        const float* xb  = Xs + b*64;
        const float* xnb = Xn + b*64;
        float acc = 0.f;
#pragma unroll 8
        for (int i = 0; i < 64; ++i)
            acc += xb[i]*Wp[i*64 + o] + xnb[i]*Wm[i*64 + o];
        g_Z[(size_t)p * MODES_ + m] = acc;
    }
}

// ---------------------------------------------------------------------------
// K3: FUSED inverse transform + W-blur(+mask) + H-blur. One block per (b,o).
// smem floats: ct[128] st[128] Zs[420(pad21)] A[1533] Bb[1533] pl[9417]
//              cmap(int)[585];  G1..P2 (4x1460) overlay pl.
// ---------------------------------------------------------------------------
__global__ void __launch_bounds__(256) k_invwh(void) {
    extern __shared__ float sm[];
    float* ct = sm;
    float* st = sm + 128;
    float* Zs = sm + 256;           // [20][21] padded
    float* A  = sm + 676;
    float* Bb = A + 1533;
    float* pl = Bb + 1533;          // stride 129, 73 cols
    float* G1 = pl;
    float* G2 = pl + 1460;
    float* P1 = pl + 2920;
    float* P2 = pl + 4380;
    int*  cmap = (int*)(sm + 13159);

    int tid = threadIdx.x;
    int bo  = blockIdx.x;
    fill_tabs_n(ct, st, 256);
    for (int i = tid; i < 400; i += 256) {
        int m1 = i / 20, m2 = i - m1*20;
        Zs[m1*21 + m2] = g_Z[(size_t)bo * MODES_ + i];
    }
    for (int idx = tid; idx < 585; idx += 256) {
        int jj = idx / 9, t = idx - jj*9;
        int w  = (jj < 33) ? jj : jj + 63;
        int ww = w + t - 4;
        ww = ww < 0 ? 0 : (ww > 127 ? 127 : ww);
        int p = (ww < 37) ? ww : ww - 55;
        cmap[idx] = p * 129;
    }
    __syncthreads();

    // phase A: lanes sweep m1 (trig broadcast, Zs conflict-free)
    const float inv = 6.103515625e-05f;
    for (int idx = tid; idx < 1460; idx += 256) {
        int j = idx / 20, m1 = idx - j*20;
        int n2 = (j < 37) ? j : j + 55;
        float g1 = 0.f, g2 = 0.f;
        int t = 0;
#pragma unroll
        for (int m2 = 0; m2 < 20; ++m2) {
            float z = Zs[m1*21 + m2];
            g1 += z * ct[t]; g2 += z * st[t];
            t = (t + n2) & 127;
        }
        g1 *= inv; g2 *= inv;
        float cb = ct[n2], sb = st[n2];
        G1[m1*73+j] = g1; G2[m1*73+j] = g2;
        P1[m1*73+j] = cb*g1 - sb*g2;
        P2[m1*73+j] = sb*g1 + cb*g2;
    }
    __syncthreads();

    for (int idx = tid; idx < 1533; idx += 256) {
        int m = idx / 73, j = idx - m*73;
        float a = 0.f, b = 0.f;
        if (m < 20) { a = G1[m*73+j]; b = G2[m*73+j]; }
        if (m > 0)  { a -= P2[(m-1)*73+j]; b += P1[(m-1)*73+j]; }
        A[idx] = a; Bb[idx] = b;
    }
    __syncthreads();

    // stage2: register trig, parity-paired outputs -> pl
    {
        int n1p   = tid & 63;
        int chunk = tid >> 6;
        float cm[21], smv[21];
#pragma unroll
        for (int m = 0; m < 21; ++m) {
            int tt = (n1p * m) & 127;
            cm[m] = ct[tt]; smv[m] = st[tt];
        }
        for (int j = chunk; j < 73; j += 4) {
            float sc = 0.f, ss = 0.f, s64 = 0.f;
#pragma unroll
            for (int m = 0; m < 21; ++m) {
                float a = A[m*73+j], b = Bb[m*73+j];
                sc += cm[m]*a; ss += smv[m]*b;
                s64 += (m & 1) ? -a : a;
            }
            pl[j*129 + n1p] = sc - ss;
            pl[j*129 + ((128 - n1p) & 127)] = sc + ss;
            if (n1p == 0) pl[j*129 + 64] = s64;
        }
    }
    __syncthreads();

    // W-blur (+mask), register-staged, in-place to 65 cols
    float acc[33];
#pragma unroll
    for (int i = 0; i < 33; ++i) {
        int idx = tid + 256*i;
        if (idx < PS_) {
            int j = idx >> 7, r = idx & 127;
            const int* cmp = cmap + j*9;
            float a = 0.f;
#pragma unroll
            for (int t = 0; t < 9; ++t) a += GK[t] * pl[cmp[t] + r];
            acc[i] = a;
        }
    }
    __syncthreads();
#pragma unroll
    for (int i = 0; i < 33; ++i) {
        int idx = tid + 256*i;
        if (idx < PS_) {
            int j = idx >> 7, r = idx & 127;
            pl[j*129 + r] = acc[i];
        }
    }
    __syncthreads();

    // H-blur -> row-major compact plane
    float* out = g_buf1 + (size_t)bo * PS_;
    for (int idx = tid; idx < PS_; idx += 256) {
        int r = idx / 65, j = idx - r*65;
        float a = 0.f;
#pragma unroll
        for (int t = 0; t < 9; ++t) {
            int rr = r + t - 4;
            rr = rr < 0 ? 0 : (rr > 127 ? 127 : rr);
            a += GK[t] * pl[j*129 + rr];
        }
        out[idx] = a;
    }
}

// K4: zero cols 32..95 of every output row with float4 (cols 32 and 96..127
// are kept columns rewritten afterwards by k_bc).
__global__ void __launch_bounds__(256) k_zero(float4* __restrict__ out) {
    int idx = blockIdx.x * 256 + threadIdx.x;   // rows*16 quads
    int row = idx >> 4, q = (idx & 15) + 8;
    out[(size_t)row * 32 + q] = make_float4(0.f, 0.f, 0.f, 0.f);
}

// K5: FUSED B-blur + C-blur over a [16][64][8-pos] tile; expands to output.
__global__ void __launch_bounds__(256) k_bc(float* __restrict__ out) {
    __shared__ float t[16*520];
    __shared__ int rr8[8], ww8[8];
    int tid = threadIdx.x;
    int p0  = blockIdx.x * 8;

    if (tid < 8) {
        int pos = p0 + tid;
        int r = pos / 65, j = pos - r*65;
        rr8[tid] = r;
        ww8[tid] = (j < 33) ? j : j + 63;
    }
    for (int idx = tid; idx < 8192; idx += 256) {
        int b = idx >> 9, rem = idx & 511;
        int c = rem >> 3, p = rem & 7;
        t[b*520 + rem] = g_buf1[(size_t)b*(CO_*PS_) + (size_t)c*PS_ + p0 + p];
    }
    __syncthreads();

    for (int task = tid; task < 512; task += 256) {
        float v[16], o[16];
#pragma unroll
        for (int b = 0; b < 16; ++b) v[b] = t[b*520 + task];
#pragma unroll
        for (int b = 0; b < 16; ++b) {
            float a = 0.f;
#pragma unroll
            for (int k = 0; k < 9; ++k) {
                int bb = b + k - 4;
                bb = bb < 0 ? 0 : (bb > 15 ? 15 : bb);
                a += GK[k] * v[bb];
            }
            o[b] = a;
        }
#pragma unroll
        for (int b = 0; b < 16; ++b) t[b*520 + task] = o[b];
    }
    __syncthreads();

    if (tid < 128) {
        int b = tid >> 3, p = tid & 7;
        float* line = t + b*520 + p;
        float win[9];
#pragma unroll
        for (int k = 0; k < 9; ++k) {
            int c = k - 4; c = c < 0 ? 0 : c;
            win[k] = line[c*8];
        }
        float res[64];
        for (int c = 0; c < 64; ++c) {
            float a = 0.f;
#pragma unroll
            for (int k = 0; k < 9; ++k) a += GK[k] * win[k];
            res[c] = a;
#pragma unroll
            for (int k = 0; k < 8; ++k) win[k] = win[k+1];
            int cn = c + 5; cn = cn > 63 ? 63 : cn;
            win[8] = line[cn*8];
        }
        for (int c = 0; c < 64; ++c) line[c*8] = res[c];
    }
    __syncthreads();

    for (int idx = tid; idx < 8192; idx += 256) {
        int b = idx >> 9, rem = idx & 511;
        int c = rem >> 3, p = rem & 7;
        out[(size_t)b*(CO_*HW_) + (size_t)c*HW_ + rr8[p]*128 + ww8[p]]
            = t[b*520 + rem];
    }
}

extern "C" void kernel_launch(void* const* d_in, const int* in_sizes, int n_in,
                              void* d_out, int out_size) {
    (void)in_sizes; (void)n_in; (void)out_size;
    const float* x  = (const float*)d_in[0];
    const float* w1 = (const float*)d_in[1];
    float* out = (float*)d_out;

    cudaFuncSetAttribute(k_fwd, cudaFuncAttributeMaxDynamicSharedMemorySize,
                         FW_SMEM);
    cudaFuncSetAttribute(k_invwh, cudaFuncAttributeMaxDynamicSharedMemorySize,
                         IW_SMEM);
    k_fwd  <<<BC_, 320, FW_SMEM>>>(x);
    k_mul  <<<MODES_, 256>>>(w1);
    k_invwh<<<BO_, 256, IW_SMEM>>>();
    k_zero <<<(B_*CO_*N_*16)/256, 256>>>((float4*)out);
    k_bc   <<<PS_/8, 256>>>(out);
}

// round 7
// speedup vs baseline: 2.1687x; 1.0378x over previous
#include <cuda_runtime.h>
#include <cstddef>

#define B_   16
#define CO_  64
#define N_   128
#define HW_  16384
#define MODES_ 400
#define BC_  1024
#define BO_  1024
#define NC_  73
#define NK_  65
#define PS_  (N_*NK_)      // 8320
#define FW_SMEM  98304     // k_fwd dynamic smem bytes
#define IW_SMEM  54976     // k_invwh dynamic smem bytes
#define WT_SMEM  51328     // k_wt dynamic smem bytes (32*401 floats)

__device__ float g_Xh[(size_t)MODES_*BC_];    // [mode][bc]
__device__ float g_Z [(size_t)MODES_*BO_];    // [mode][bo]
__device__ float g_WpT[(size_t)MODES_*4096];  // [mode][ci*64+co]
__device__ float g_WmT[(size_t)MODES_*4096];
__device__ float g_buf1[(size_t)BO_*PS_];

__constant__ float GK[9] = {
    1.3383062e-04f, 4.4318606e-03f, 5.3991128e-02f, 2.4197145e-01f,
    3.9894348e-01f, 2.4197145e-01f, 5.3991128e-02f, 4.4318606e-03f,
    1.3383062e-04f
};

__device__ __forceinline__ void fill_tabs_n(float* ct, float* st, int nthr) {
    const float w = 6.283185307179586f / 128.0f;
    for (int t = threadIdx.x; t < 128; t += nthr) {
        float s, c;
        sincosf(w * (float)t, &s, &c);
        ct[t] = c; st[t] = s;
    }
}

// ---------------------------------------------------------------------------
// K0: transpose + fold weights once: WpT[m][i]=0.5(w[i][m]+w[i][mn]), WmT=diff
// Tile-transposed through smem so both sides are coalesced / conflict-free.
// ---------------------------------------------------------------------------
__global__ void __launch_bounds__(256) k_wt(const float* __restrict__ w1) {
    extern __shared__ float ws[];            // [32][401]
    int i0 = blockIdx.x * 32;
    for (int idx = threadIdx.x; idx < 32*400; idx += 256) {
        int r = idx / 400, m = idx - r*400;
        ws[r*401 + m] = w1[(size_t)(i0 + r)*400 + m];
    }
    __syncthreads();
    for (int idx = threadIdx.x; idx < 12800; idx += 256) {
        int m = idx >> 5, r = idx & 31;
        int m1 = m / 20, m2 = m - m1*20;
        int mn = ((20 - m1) % 20) * 20 + ((20 - m2) % 20);
        float w  = ws[r*401 + m];
        float wn = ws[r*401 + mn];
        g_WpT[(size_t)m*4096 + i0 + r] = 0.5f*(w + wn);
        g_WmT[(size_t)m*4096 + i0 + r] = 0.5f*(w - wn);
    }
}

// ---------------------------------------------------------------------------
// K1: forward truncated DHT. Stage1 GEMM (reg-tiled); stage2 via padded
// TC/TS[20][65] trig matrices (conflict-free). Out: g_Xh[mode][bc].
// ---------------------------------------------------------------------------
__global__ void __launch_bounds__(320) k_fwd(const float* __restrict__ x) {
    extern __shared__ float sm[];
    float* ct = sm;             // 128
    float* st = sm + 128;       // 128
    float* CT = sm + 256;       // 64*20
    float* ST = CT + 1280;      // 64*20
    float* xp = ST + 1280;      // 128*65
    float* xm = xp + 8320;      // 128*65
    float* U  = xm + 8320;      // 128*20
    float* V  = U + 2560;       // 128*20
    float* F1 = xp;             // overlay after GEMM ([64][20])
    float* F2 = xm;
    float* TC = U;              // overlay after F-build ([20][65])
    float* TS = V;

    int tid = threadIdx.x;
    int bc  = blockIdx.x;
    const float* xb = x + (size_t)bc * HW_;

    fill_tabs_n(ct, st, 320);
    __syncthreads();

    for (int idx = tid; idx < 1280; idx += 320) {
        int q = idx / 20, k2 = idx - q*20;
        if (q == 0) { CT[idx] = 1.f; ST[idx] = 0.f; }
        else {
            int t = (q * k2) & 127;
            CT[idx] = ct[t]; ST[idx] = st[t];
        }
    }
    for (int idx = tid; idx < 8192; idx += 320) {
        int r = idx >> 6, q = idx & 63;
        const float* row = xb + r * 128;
        if (q == 0) { xp[r*65] = row[0]; xm[r*65] = row[64]; }
        else {
            float a = row[q], b = row[128 - q];
            xp[r*65 + q] = a + b; xm[r*65 + q] = a - b;
        }
    }
    __syncthreads();

    {   // stage1 GEMM
        int ty = tid & 31, tx = tid >> 5;
        int isU = (tx < 5);
        int c0  = (isU ? tx : tx - 5) * 4;
        const float* A  = isU ? xp : xm;
        const float* Bm = isU ? CT : ST;
        float acc[4][4];
#pragma unroll
        for (int i = 0; i < 4; ++i)
#pragma unroll
            for (int j = 0; j < 4; ++j) acc[i][j] = 0.f;
#pragma unroll 4
        for (int q = 0; q < 64; ++q) {
            float b0 = Bm[q*20 + c0];
            float b1 = Bm[q*20 + c0 + 1];
            float b2 = Bm[q*20 + c0 + 2];
            float b3 = Bm[q*20 + c0 + 3];
#pragma unroll
            for (int i = 0; i < 4; ++i) {
                float a = A[(ty + 32*i)*65 + q];
                acc[i][0] += a*b0; acc[i][1] += a*b1;
                acc[i][2] += a*b2; acc[i][3] += a*b3;
            }
        }
        float* O = isU ? U : V;
#pragma unroll
        for (int i = 0; i < 4; ++i) {
            float pm = isU ? xm[(ty + 32*i)*65] : 0.f;
#pragma unroll
            for (int j = 0; j < 4; ++j) {
                float v = acc[i][j];
                if (isU) v += ((c0 + j) & 1) ? -pm : pm;
                O[(ty + 32*i)*20 + c0 + j] = v;
            }
        }
    }
    __syncthreads();

    // F build (E-fold + parity) into F1/F2 (overlay xp/xm)
    for (int idx = tid; idx < 1280; idx += 320) {
        int n = idx / 20, k2 = idx - n*20;
        float cd = ct[k2], sd = st[k2];
        if (n == 0) {
            F1[k2] = U[0*20+k2]  - (sd*U[127*20+k2] + cd*V[127*20+k2]);
            F2[k2] = U[64*20+k2] - (sd*U[63*20+k2]  + cd*V[63*20+k2]);
        } else {
            int nm = n - 1, nn = 128 - n, nnm = 127 - n;
            float e1a = U[n*20+k2]  - (sd*U[nm*20+k2]  + cd*V[nm*20+k2]);
            float e2a = V[n*20+k2]  + (cd*U[nm*20+k2]  - sd*V[nm*20+k2]);
            float e1b = U[nn*20+k2] - (sd*U[nnm*20+k2] + cd*V[nnm*20+k2]);
            float e2b = V[nn*20+k2] + (cd*U[nnm*20+k2] - sd*V[nnm*20+k2]);
            F1[n*20 + k2] = e1a + e1b;
            F2[n*20 + k2] = e2a - e2b;
        }
    }
    __syncthreads();

    // build TC/TS (overlay U/V): TC[k1][0]=1, TS[k1][0]=-sign(k1)
    for (int idx = tid; idx < 1300; idx += 320) {
        int k1 = idx / 65, n = idx - k1*65;
        if (n == 0)      { TC[idx] = 1.f; TS[idx] = (k1 & 1) ? 1.f : -1.f; }
        else if (n < 64) { int t = (k1*n) & 127; TC[idx] = ct[t]; TS[idx] = st[t]; }
    }
    __syncthreads();

    // stage2: lanes sweep k1 -> TC/TS conflict-free (bank=(k1+n)%32)
    for (int o = tid; o < 400; o += 320) {
        int k1 = o % 20, k2 = o / 20;
        float acc = 0.f;
#pragma unroll 8
        for (int n = 0; n < 64; ++n)
            acc += TC[k1*65+n]*F1[n*20+k2] - TS[k1*65+n]*F2[n*20+k2];
        g_Xh[(size_t)(k1*20 + k2)*BC_ + bc] = acc;
    }
}

// ---------------------------------------------------------------------------
// K2: folded compl_mul2d, all loads/stores coalesced via transposed layouts.
// ---------------------------------------------------------------------------
__global__ void __launch_bounds__(256) k_mul(void) {
    __shared__ float Xs[1024], Xn[1024], Wp[4096], Wm[4096];
    int m  = blockIdx.x;
    int m1 = m / 20, m2 = m % 20;
    int mn = ((20 - m1) % 20) * 20 + ((20 - m2) % 20);

    for (int i = threadIdx.x; i < 1024; i += 256) {
        Xs[i] = g_Xh[(size_t)m  * BC_ + i];
        Xn[i] = g_Xh[(size_t)mn * BC_ + i];
    }
    for (int i = threadIdx.x; i < 4096; i += 256) {
        Wp[i] = g_WpT[(size_t)m*4096 + i];
        Wm[i] = g_WmT[(size_t)m*4096 + i];
    }
    __syncthreads();

    for (int p = threadIdx.x; p < 1024; p += 256) {
        int b = p >> 6, o = p & 63;
        const float* xb  = Xs + b*64;
        const float* xnb = Xn + b*64;
        float acc = 0.f;
#pragma unroll 8
        for (int i = 0; i < 64; ++i)
            acc += xb[i]*Wp[i*64 + o] + xnb[i]*Wm[i*64 + o];
        g_Z[(size_t)m * BO_ + p] = acc;   // coalesced store
    }
}

// ---------------------------------------------------------------------------
// K3: FUSED inverse transform + W-blur(+mask) + H-blur. One block per (b,o).
// ---------------------------------------------------------------------------
__global__ void __launch_bounds__(256) k_invwh(void) {
    extern __shared__ float sm[];
    float* ct = sm;
    float* st = sm + 128;
    float* Zs = sm + 256;           // [20][21] padded
    float* A  = sm + 676;
    float* Bb = A + 1533;
    float* pl = Bb + 1533;          // stride 129, 73 cols
    float* G1 = pl;
    float* G2 = pl + 1460;
    float* P1 = pl + 2920;
    float* P2 = pl + 4380;
    int*  cmap = (int*)(sm + 13159);

    int tid = threadIdx.x;
    int bo  = blockIdx.x;
    fill_tabs_n(ct, st, 256);
    for (int i = tid; i < 400; i += 256) {
        int m1 = i / 20, m2 = i - m1*20;
        Zs[m1*21 + m2] = g_Z[(size_t)i * BO_ + bo];
    }
    for (int idx = tid; idx < 585; idx += 256) {
        int jj = idx / 9, t = idx - jj*9;
        int w  = (jj < 33) ? jj : jj + 63;
        int ww = w + t - 4;
        ww = ww < 0 ? 0 : (ww > 127 ? 127 : ww);
        int p = (ww < 37) ? ww : ww - 55;
        cmap[idx] = p * 129;
    }
    __syncthreads();

    const float inv = 6.103515625e-05f;
    for (int idx = tid; idx < 1460; idx += 256) {
        int j = idx / 20, m1 = idx - j*20;
        int n2 = (j < 37) ? j : j + 55;
        float g1 = 0.f, g2 = 0.f;
        int t = 0;
#pragma unroll
        for (int m2 = 0; m2 < 20; ++m2) {
            float z = Zs[m1*21 + m2];
            g1 += z * ct[t]; g2 += z * st[t];
            t = (t + n2) & 127;
        }
        g1 *= inv; g2 *= inv;
        float cb = ct[n2], sb = st[n2];
        G1[m1*73+j] = g1; G2[m1*73+j] = g2;
        P1[m1*73+j] = cb*g1 - sb*g2;
        P2[m1*73+j] = sb*g1 + cb*g2;
    }
    __syncthreads();

    for (int idx = tid; idx < 1533; idx += 256) {
        int m = idx / 73, j = idx - m*73;
        float a = 0.f, b = 0.f;
        if (m < 20) { a = G1[m*73+j]; b = G2[m*73+j]; }
        if (m > 0)  { a -= P2[(m-1)*73+j]; b += P1[(m-1)*73+j]; }
        A[idx] = a; Bb[idx] = b;
    }
    __syncthreads();

    {
        int n1p   = tid & 63;
        int chunk = tid >> 6;
        float cm[21], smv[21];
#pragma unroll
        for (int m = 0; m < 21; ++m) {
            int tt = (n1p * m) & 127;
            cm[m] = ct[tt]; smv[m] = st[tt];
        }
        for (int j = chunk; j < 73; j += 4) {
            float sc = 0.f, ss = 0.f, s64 = 0.f;
#pragma unroll
            for (int m = 0; m < 21; ++m) {
                float a = A[m*73+j], b = Bb[m*73+j];
                sc += cm[m]*a; ss += smv[m]*b;
                s64 += (m & 1) ? -a : a;
            }
            pl[j*129 + n1p] = sc - ss;
            pl[j*129 + ((128 - n1p) & 127)] = sc + ss;
            if (n1p == 0) pl[j*129 + 64] = s64;
        }
    }
    __syncthreads();

    float acc[33];
#pragma unroll
    for (int i = 0; i < 33; ++i) {
        int idx = tid + 256*i;
        if (idx < PS_) {
            int j = idx >> 7, r = idx & 127;
            const int* cmp = cmap + j*9;
            float a = 0.f;
#pragma unroll
            for (int t = 0; t < 9; ++t) a += GK[t] * pl[cmp[t] + r];
            acc[i] = a;
        }
    }
    __syncthreads();
#pragma unroll
    for (int i = 0; i < 33; ++i) {
        int idx = tid + 256*i;
        if (idx < PS_) {
            int j = idx >> 7, r = idx & 127;
            pl[j*129 + r] = acc[i];
        }
    }
    __syncthreads();

    float* out = g_buf1 + (size_t)bo * PS_;
    for (int idx = tid; idx < PS_; idx += 256) {
        int r = idx / 65, j = idx - r*65;
        float a = 0.f;
#pragma unroll
        for (int t = 0; t < 9; ++t) {
            int rr = r + t - 4;
            rr = rr < 0 ? 0 : (rr > 127 ? 127 : rr);
            a += GK[t] * pl[j*129 + rr];
        }
        out[idx] = a;
    }
}

// K4: zero cols 32..95 of every output row (float4).
__global__ void __launch_bounds__(256) k_zero(float4* __restrict__ out) {
    int idx = blockIdx.x * 256 + threadIdx.x;
    int row = idx >> 4, q = (idx & 15) + 8;
    out[(size_t)row * 32 + q] = make_float4(0.f, 0.f, 0.f, 0.f);
}

// K5: FUSED B-blur + C-blur over [16][64][8-pos] tile; expands to output.
__global__ void __launch_bounds__(256) k_bc(float* __restrict__ out) {
    __shared__ float t[16*520];
    __shared__ int rr8[8], ww8[8];
    int tid = threadIdx.x;
    int p0  = blockIdx.x * 8;

    if (tid < 8) {
        int pos = p0 + tid;
        int r = pos / 65, j = pos - r*65;
        rr8[tid] = r;
        ww8[tid] = (j < 33) ? j : j + 63;
    }
    for (int idx = tid; idx < 8192; idx += 256) {
        int b = idx >> 9, rem = idx & 511;
        int c = rem >> 3, p = rem & 7;
        t[b*520 + rem] = g_buf1[(size_t)b*(CO_*PS_) + (size_t)c*PS_ + p0 + p];
    }
    __syncthreads();

    // B-blur: thread owns (c,p) columns exclusively
    for (int task = tid; task < 512; task += 256) {
        float v[16], o[16];
#pragma unroll
        for (int b = 0; b < 16; ++b) v[b] = t[b*520 + task];
#pragma unroll
        for (int b = 0; b < 16; ++b) {
            float a = 0.f;
#pragma unroll
            for (int k = 0; k < 9; ++k) {
                int bb = b + k - 4;
                bb = bb < 0 ? 0 : (bb > 15 ? 15 : bb);
                a += GK[k] * v[bb];
            }
            o[b] = a;
        }
#pragma unroll
        for (int b = 0; b < 16; ++b) t[b*520 + task] = o[b];
    }
    __syncthreads();

    // C-blur: all 256 threads, thread = (b, p, half-line of 32 c)
    float cres[32];
    {
        int b = tid >> 4, p = (tid >> 1) & 7, half = tid & 1;
        const float* line = t + b*520 + p;
        int cbeg = half * 32;
        float win[9];
#pragma unroll
        for (int k = 0; k < 9; ++k) {
            int c = cbeg + k - 4; c = c < 0 ? 0 : (c > 63 ? 63 : c);
            win[k] = line[c*8];
        }
#pragma unroll
        for (int q = 0; q < 32; ++q) {
            float a = 0.f;
#pragma unroll
            for (int k = 0; k < 9; ++k) a += GK[k] * win[k];
            cres[q] = a;
#pragma unroll
            for (int k = 0; k < 8; ++k) win[k] = win[k+1];
            int cn = cbeg + q + 5; cn = cn > 63 ? 63 : cn;
            win[8] = line[cn*8];
        }
    }
    __syncthreads();
    {
        int b = tid >> 4, p = (tid >> 1) & 7, half = tid & 1;
        float* line = t + b*520 + p;
#pragma unroll
        for (int q = 0; q < 32; ++q) line[(half*32 + q)*8] = cres[q];
    }
    __syncthreads();

    for (int idx = tid; idx < 8192; idx += 256) {
        int b = idx >> 9, rem = idx & 511;
        int c = rem >> 3, p = rem & 7;
        out[(size_t)b*(CO_*HW_) + (size_t)c*HW_ + rr8[p]*128 + ww8[p]]
            = t[b*520 + rem];
    }
}

extern "C" void kernel_launch(void* const* d_in, const int* in_sizes, int n_in,
                              void* d_out, int out_size) {
    (void)in_sizes; (void)n_in; (void)out_size;
    const float* x  = (const float*)d_in[0];
    const float* w1 = (const float*)d_in[1];
    float* out = (float*)d_out;

    cudaFuncSetAttribute(k_fwd, cudaFuncAttributeMaxDynamicSharedMemorySize,
                         FW_SMEM);
    cudaFuncSetAttribute(k_invwh, cudaFuncAttributeMaxDynamicSharedMemorySize,
                         IW_SMEM);
    cudaFuncSetAttribute(k_wt, cudaFuncAttributeMaxDynamicSharedMemorySize,
                         WT_SMEM);
    k_wt   <<<128, 256, WT_SMEM>>>(w1);
    k_fwd  <<<BC_, 320, FW_SMEM>>>(x);
    k_mul  <<<MODES_, 256>>>();
    k_invwh<<<BO_, 256, IW_SMEM>>>();
    k_zero <<<(B_*CO_*N_*16)/256, 256>>>((float4*)out);
    k_bc   <<<PS_/8, 256>>>(out);
}

// round 8
// speedup vs baseline: 2.4029x; 1.1080x over previous
#include <cuda_runtime.h>
#include <cstddef>

#define B_   16
#define CO_  64
#define N_   128
#define HW_  16384
#define MODES_ 400
#define BC_  1024
#define BO_  1024
#define NC_  73
#define NK_  65
#define PS_  (N_*NK_)      // 8320
#define FW_SMEM  98304     // k_fwd dynamic smem bytes
#define IW_SMEM  52640     // k_invwh dynamic smem bytes (13160 floats)
#define WT_SMEM  51328     // k_wt dynamic smem bytes (32*401 floats)

__device__ float g_Xh[(size_t)MODES_*BC_];    // [mode][bc]
__device__ float g_Z [(size_t)MODES_*BO_];    // [mode][bo]
__device__ float g_WpT[(size_t)MODES_*4096];  // [mode][ci*64+co]
__device__ float g_WmT[(size_t)MODES_*4096];
__device__ float g_buf1[(size_t)BO_*PS_];

__constant__ float GK[9] = {
    1.3383062e-04f, 4.4318606e-03f, 5.3991128e-02f, 2.4197145e-01f,
    3.9894348e-01f, 2.4197145e-01f, 5.3991128e-02f, 4.4318606e-03f,
    1.3383062e-04f
};

__device__ __forceinline__ void fill_tabs_n(float* ct, float* st, int nthr) {
    const float w = 6.283185307179586f / 128.0f;
    for (int t = threadIdx.x; t < 128; t += nthr) {
        float s, c;
        sincosf(w * (float)t, &s, &c);
        ct[t] = c; st[t] = s;
    }
}

// ---------------------------------------------------------------------------
// K0: transpose + fold weights once: WpT[m][i]=0.5(w[i][m]+w[i][mn]), WmT=diff
// ---------------------------------------------------------------------------
__global__ void __launch_bounds__(256) k_wt(const float* __restrict__ w1) {
    extern __shared__ float ws[];            // [32][401]
    int i0 = blockIdx.x * 32;
    for (int idx = threadIdx.x; idx < 32*400; idx += 256) {
        int r = idx / 400, m = idx - r*400;
        ws[r*401 + m] = w1[(size_t)(i0 + r)*400 + m];
    }
    __syncthreads();
    for (int idx = threadIdx.x; idx < 12800; idx += 256) {
        int m = idx >> 5, r = idx & 31;
        int m1 = m / 20, m2 = m - m1*20;
        int mn = ((20 - m1) % 20) * 20 + ((20 - m2) % 20);
        float w  = ws[r*401 + m];
        float wn = ws[r*401 + mn];
        g_WpT[(size_t)m*4096 + i0 + r] = 0.5f*(w + wn);
        g_WmT[(size_t)m*4096 + i0 + r] = 0.5f*(w - wn);
    }
}

// ---------------------------------------------------------------------------
// K1: forward truncated DHT. Stage1 GEMM (reg-tiled); stage2 via padded
// TC/TS[20][65] trig matrices. Out: g_Xh[mode][bc].
// ---------------------------------------------------------------------------
__global__ void __launch_bounds__(320) k_fwd(const float* __restrict__ x) {
    extern __shared__ float sm[];
    float* ct = sm;             // 128
    float* st = sm + 128;       // 128
    float* CT = sm + 256;       // 64*20
    float* ST = CT + 1280;      // 64*20
    float* xp = ST + 1280;      // 128*65
    float* xm = xp + 8320;      // 128*65
    float* U  = xm + 8320;      // 128*20
    float* V  = U + 2560;       // 128*20
    float* F1 = xp;             // overlay after GEMM ([64][20])
    float* F2 = xm;
    float* TC = U;              // overlay after F-build ([20][65])
    float* TS = V;

    int tid = threadIdx.x;
    int bc  = blockIdx.x;
    const float* xb = x + (size_t)bc * HW_;

    fill_tabs_n(ct, st, 320);
    __syncthreads();

    for (int idx = tid; idx < 1280; idx += 320) {
        int q = idx / 20, k2 = idx - q*20;
        if (q == 0) { CT[idx] = 1.f; ST[idx] = 0.f; }
        else {
            int t = (q * k2) & 127;
            CT[idx] = ct[t]; ST[idx] = st[t];
        }
    }
    for (int idx = tid; idx < 8192; idx += 320) {
        int r = idx >> 6, q = idx & 63;
        const float* row = xb + r * 128;
        if (q == 0) { xp[r*65] = row[0]; xm[r*65] = row[64]; }
        else {
            float a = row[q], b = row[128 - q];
            xp[r*65 + q] = a + b; xm[r*65 + q] = a - b;
        }
    }
    __syncthreads();

    {   // stage1 GEMM
        int ty = tid & 31, tx = tid >> 5;
        int isU = (tx < 5);
        int c0  = (isU ? tx : tx - 5) * 4;
        const float* A  = isU ? xp : xm;
        const float* Bm = isU ? CT : ST;
        float acc[4][4];
#pragma unroll
        for (int i = 0; i < 4; ++i)
#pragma unroll
            for (int j = 0; j < 4; ++j) acc[i][j] = 0.f;
#pragma unroll 4
        for (int q = 0; q < 64; ++q) {
            float b0 = Bm[q*20 + c0];
            float b1 = Bm[q*20 + c0 + 1];
            float b2 = Bm[q*20 + c0 + 2];
            float b3 = Bm[q*20 + c0 + 3];
#pragma unroll
            for (int i = 0; i < 4; ++i) {
                float a = A[(ty + 32*i)*65 + q];
                acc[i][0] += a*b0; acc[i][1] += a*b1;
                acc[i][2] += a*b2; acc[i][3] += a*b3;
            }
        }
        float* O = isU ? U : V;
#pragma unroll
        for (int i = 0; i < 4; ++i) {
            float pm = isU ? xm[(ty + 32*i)*65] : 0.f;
#pragma unroll
            for (int j = 0; j < 4; ++j) {
                float v = acc[i][j];
                if (isU) v += ((c0 + j) & 1) ? -pm : pm;
                O[(ty + 32*i)*20 + c0 + j] = v;
            }
        }
    }
    __syncthreads();

    for (int idx = tid; idx < 1280; idx += 320) {
        int n = idx / 20, k2 = idx - n*20;
        float cd = ct[k2], sd = st[k2];
        if (n == 0) {
            F1[k2] = U[0*20+k2]  - (sd*U[127*20+k2] + cd*V[127*20+k2]);
            F2[k2] = U[64*20+k2] - (sd*U[63*20+k2]  + cd*V[63*20+k2]);
        } else {
            int nm = n - 1, nn = 128 - n, nnm = 127 - n;
            float e1a = U[n*20+k2]  - (sd*U[nm*20+k2]  + cd*V[nm*20+k2]);
            float e2a = V[n*20+k2]  + (cd*U[nm*20+k2]  - sd*V[nm*20+k2]);
            float e1b = U[nn*20+k2] - (sd*U[nnm*20+k2] + cd*V[nnm*20+k2]);
            float e2b = V[nn*20+k2] + (cd*U[nnm*20+k2] - sd*V[nnm*20+k2]);
            F1[n*20 + k2] = e1a + e1b;
            F2[n*20 + k2] = e2a - e2b;
        }
    }
    __syncthreads();

    for (int idx = tid; idx < 1300; idx += 320) {
        int k1 = idx / 65, n = idx - k1*65;
        if (n == 0)      { TC[idx] = 1.f; TS[idx] = (k1 & 1) ? 1.f : -1.f; }
        else if (n < 64) { int t = (k1*n) & 127; TC[idx] = ct[t]; TS[idx] = st[t]; }
    }
    __syncthreads();

    for (int o = tid; o < 400; o += 320) {
        int k1 = o % 20, k2 = o / 20;
        float acc = 0.f;
#pragma unroll 8
        for (int n = 0; n < 64; ++n)
            acc += TC[k1*65+n]*F1[n*20+k2] - TS[k1*65+n]*F2[n*20+k2];
        g_Xh[(size_t)(k1*20 + k2)*BC_ + bc] = acc;
    }
}

// ---------------------------------------------------------------------------
// K2: folded compl_mul2d, fully coalesced.
// ---------------------------------------------------------------------------
__global__ void __launch_bounds__(256) k_mul(void) {
    __shared__ float Xs[1024], Xn[1024], Wp[4096], Wm[4096];
    int m  = blockIdx.x;
    int m1 = m / 20, m2 = m % 20;
    int mn = ((20 - m1) % 20) * 20 + ((20 - m2) % 20);

    for (int i = threadIdx.x; i < 1024; i += 256) {
        Xs[i] = g_Xh[(size_t)m  * BC_ + i];
        Xn[i] = g_Xh[(size_t)mn * BC_ + i];
    }
    for (int i = threadIdx.x; i < 4096; i += 256) {
        Wp[i] = g_WpT[(size_t)m*4096 + i];
        Wm[i] = g_WmT[(size_t)m*4096 + i];
    }
    __syncthreads();

    for (int p = threadIdx.x; p < 1024; p += 256) {
        int b = p >> 6, o = p & 63;
        const float* xb  = Xs + b*64;
        const float* xnb = Xn + b*64;
        float acc = 0.f;
#pragma unroll 8
        for (int i = 0; i < 64; ++i)
            acc += xb[i]*Wp[i*64 + o] + xnb[i]*Wm[i*64 + o];
        g_Z[(size_t)m * BO_ + p] = acc;
    }
}

// ---------------------------------------------------------------------------
// K3: FUSED inverse transform + W-blur(+mask) + H-blur. One block per (b,o).
// smem floats: ct[128] st[128] Zs[420] A[1533] Bb[1533] pl[9417]
// ---------------------------------------------------------------------------
__global__ void __launch_bounds__(256) k_invwh(void) {
    extern __shared__ float sm[];
    float* ct = sm;
    float* st = sm + 128;
    float* Zs = sm + 256;           // [20][21] padded
    float* A  = sm + 676;
    float* Bb = A + 1533;
    float* pl = Bb + 1533;          // stride 129, 73 cols
    float* G1 = pl;
    float* G2 = pl + 1460;
    float* P1 = pl + 2920;
    float* P2 = pl + 4380;

    int tid = threadIdx.x;
    int bo  = blockIdx.x;
    fill_tabs_n(ct, st, 256);
    for (int i = tid; i < 400; i += 256) {
        int m1 = i / 20, m2 = i - m1*20;
        Zs[m1*21 + m2] = g_Z[(size_t)i * BO_ + bo];
    }
    __syncthreads();

    // phase A: m1-register-tiled (4 per thread); trig amortized 4x
    const float inv = 6.103515625e-05f;
    for (int task = tid; task < 365; task += 256) {
        int j = task / 5, g = task - j*5;
        int m1b = g * 4;
        int n2 = (j < 37) ? j : j + 55;
        float a0=0.f,a1=0.f,a2=0.f,a3=0.f;
        float b0=0.f,b1=0.f,b2=0.f,b3=0.f;
        int t = 0;
#pragma unroll
        for (int m2 = 0; m2 < 20; ++m2) {
            float c = ct[t], s = st[t];
            float z0 = Zs[(m1b+0)*21 + m2];
            float z1 = Zs[(m1b+1)*21 + m2];
            float z2 = Zs[(m1b+2)*21 + m2];
            float z3 = Zs[(m1b+3)*21 + m2];
            a0 += z0*c; b0 += z0*s;
            a1 += z1*c; b1 += z1*s;
            a2 += z2*c; b2 += z2*s;
            a3 += z3*c; b3 += z3*s;
            t = (t + n2) & 127;
        }
        float cb = ct[n2], sb = st[n2];
        float ga[4] = {a0*inv, a1*inv, a2*inv, a3*inv};
        float gb[4] = {b0*inv, b1*inv, b2*inv, b3*inv};
#pragma unroll
        for (int u = 0; u < 4; ++u) {
            int m1 = m1b + u;
            G1[m1*73+j] = ga[u]; G2[m1*73+j] = gb[u];
            P1[m1*73+j] = cb*ga[u] - sb*gb[u];
            P2[m1*73+j] = sb*ga[u] + cb*gb[u];
        }
    }
    __syncthreads();

    for (int idx = tid; idx < 1533; idx += 256) {
        int m = idx / 73, j = idx - m*73;
        float a = 0.f, b = 0.f;
        if (m < 20) { a = G1[m*73+j]; b = G2[m*73+j]; }
        if (m > 0)  { a -= P2[(m-1)*73+j]; b += P1[(m-1)*73+j]; }
        A[idx] = a; Bb[idx] = b;
    }
    __syncthreads();

    // stage2: register trig, parity-paired outputs -> pl
    {
        int n1p   = tid & 63;
        int chunk = tid >> 6;
        float cm[21], smv[21];
#pragma unroll
        for (int m = 0; m < 21; ++m) {
            int tt = (n1p * m) & 127;
            cm[m] = ct[tt]; smv[m] = st[tt];
        }
        for (int j = chunk; j < 73; j += 4) {
            float sc = 0.f, ss = 0.f, s64 = 0.f;
#pragma unroll
            for (int m = 0; m < 21; ++m) {
                float a = A[m*73+j], b = Bb[m*73+j];
                sc += cm[m]*a; ss += smv[m]*b;
                s64 += (m & 1) ? -a : a;
            }
            pl[j*129 + n1p] = sc - ss;
            pl[j*129 + ((128 - n1p) & 127)] = sc + ss;
            if (n1p == 0) pl[j*129 + 64] = s64;
        }
    }
    __syncthreads();

    // W-blur (+mask): sliding window over contiguous tap columns per segment.
    // seg0: outputs j=0..32 (taps p 0..36, left clamp)
    // seg1: outputs j=33..64 (taps p 37..72, right clamp)
    {
        int r = tid & 127, seg = tid >> 7;
        float acc[33];
        float win[9];
        if (seg == 0) {
#pragma unroll
            for (int k = 0; k < 9; ++k) {
                int p = k - 4; p = p < 0 ? 0 : p;
                win[k] = pl[p*129 + r];
            }
            for (int j = 0; j < 33; ++j) {
                float a = 0.f;
#pragma unroll
                for (int k = 0; k < 9; ++k) a += GK[k] * win[k];
                acc[j] = a;
#pragma unroll
                for (int k = 0; k < 8; ++k) win[k] = win[k+1];
                win[8] = pl[(j + 5)*129 + r];   // j+5 <= 37 never read: j<=31 -> <=36
            }
        } else {
#pragma unroll
            for (int k = 0; k < 9; ++k)
                win[k] = pl[(37 + k)*129 + r];
            for (int q = 0; q < 32; ++q) {
                float a = 0.f;
#pragma unroll
                for (int k = 0; k < 9; ++k) a += GK[k] * win[k];
                acc[q] = a;
#pragma unroll
                for (int k = 0; k < 8; ++k) win[k] = win[k+1];
                int pn = 46 + q; pn = pn > 72 ? 72 : pn;
                win[8] = pl[pn*129 + r];
            }
        }
        __syncthreads();
        if (seg == 0) {
            for (int j = 0; j < 33; ++j) pl[j*129 + r] = acc[j];
        } else {
            for (int q = 0; q < 32; ++q) pl[(33 + q)*129 + r] = acc[q];
        }
    }
    __syncthreads();

    // H-blur: sliding window along r, store direct to global.
    {
        float* out = g_buf1 + (size_t)bo * PS_;
        for (int task = tid; task < 260; task += 256) {
            int seg = task / 65, j = task - seg*65;
            int r0 = seg * 32;
            float win[9];
#pragma unroll
            for (int k = 0; k < 9; ++k) {
                int rr = r0 + k - 4;
                rr = rr < 0 ? 0 : rr;
                win[k] = pl[j*129 + rr];
            }
            for (int q = 0; q < 32; ++q) {
                float a = 0.f;
#pragma unroll
                for (int k = 0; k < 9; ++k) a += GK[k] * win[k];
                out[(r0 + q)*65 + j] = a;
#pragma unroll
                for (int k = 0; k < 8; ++k) win[k] = win[k+1];
                int rn = r0 + q + 5; rn = rn > 127 ? 127 : rn;
                win[8] = pl[j*129 + rn];
            }
        }
    }
}

// K4: zero cols 32..95 of every output row (float4).
__global__ void __launch_bounds__(256) k_zero(float4* __restrict__ out) {
    int idx = blockIdx.x * 256 + threadIdx.x;
    int row = idx >> 4, q = (idx & 15) + 8;
    out[(size_t)row * 32 + q] = make_float4(0.f, 0.f, 0.f, 0.f);
}

// K5: FUSED B-blur + C-blur over [16][64][8-pos] tile; expands to output.
__global__ void __launch_bounds__(256) k_bc(float* __restrict__ out) {
    __shared__ float t[16*520];
    __shared__ int rr8[8], ww8[8];
    int tid = threadIdx.x;
    int p0  = blockIdx.x * 8;

    if (tid < 8) {
        int pos = p0 + tid;
        int r = pos / 65, j = pos - r*65;
        rr8[tid] = r;
        ww8[tid] = (j < 33) ? j : j + 63;
    }
    for (int idx = tid; idx < 8192; idx += 256) {
        int b = idx >> 9, rem = idx & 511;
        int c = rem >> 3, p = rem & 7;
        t[b*520 + rem] = g_buf1[(size_t)b*(CO_*PS_) + (size_t)c*PS_ + p0 + p];
    }
    __syncthreads();

    for (int task = tid; task < 512; task += 256) {
        float v[16], o[16];
#pragma unroll
        for (int b = 0; b < 16; ++b) v[b] = t[b*520 + task];
#pragma unroll
        for (int b = 0; b < 16; ++b) {
            float a = 0.f;
#pragma unroll
            for (int k = 0; k < 9; ++k) {
                int bb = b + k - 4;
                bb = bb < 0 ? 0 : (bb > 15 ? 15 : bb);
                a += GK[k] * v[bb];
            }
            o[b] = a;
        }
#pragma unroll
        for (int b = 0; b < 16; ++b) t[b*520 + task] = o[b];
    }
    __syncthreads();

    float cres[32];
    {
        int b = tid >> 4, p = (tid >> 1) & 7, half = tid & 1;
        const float* line = t + b*520 + p;
        int cbeg = half * 32;
        float win[9];
#pragma unroll
        for (int k = 0; k < 9; ++k) {
            int c = cbeg + k - 4; c = c < 0 ? 0 : (c > 63 ? 63 : c);
            win[k] = line[c*8];
        }
#pragma unroll
        for (int q = 0; q < 32; ++q) {
            float a = 0.f;
#pragma unroll
            for (int k = 0; k < 9; ++k) a += GK[k] * win[k];
            cres[q] = a;
#pragma unroll
            for (int k = 0; k < 8; ++k) win[k] = win[k+1];
            int cn = cbeg + q + 5; cn = cn > 63 ? 63 : cn;
            win[8] = line[cn*8];
        }
    }
    __syncthreads();
    {
        int b = tid >> 4, p = (tid >> 1) & 7, half = tid & 1;
        float* line = t + b*520 + p;
#pragma unroll
        for (int q = 0; q < 32; ++q) line[(half*32 + q)*8] = cres[q];
    }
    __syncthreads();

    for (int idx = tid; idx < 8192; idx += 256) {
        int b = idx >> 9, rem = idx & 511;
        int c = rem >> 3, p = rem & 7;
        out[(size_t)b*(CO_*HW_) + (size_t)c*HW_ + rr8[p]*128 + ww8[p]]
            = t[b*520 + rem];
    }
}

extern "C" void kernel_launch(void* const* d_in, const int* in_sizes, int n_in,
                              void* d_out, int out_size) {
    (void)in_sizes; (void)n_in; (void)out_size;
    const float* x  = (const float*)d_in[0];
    const float* w1 = (const float*)d_in[1];
    float* out = (float*)d_out;

    cudaFuncSetAttribute(k_fwd, cudaFuncAttributeMaxDynamicSharedMemorySize,
                         FW_SMEM);
    cudaFuncSetAttribute(k_invwh, cudaFuncAttributeMaxDynamicSharedMemorySize,
                         IW_SMEM);
    cudaFuncSetAttribute(k_wt, cudaFuncAttributeMaxDynamicSharedMemorySize,
                         WT_SMEM);
    k_wt   <<<128, 256, WT_SMEM>>>(w1);
    k_fwd  <<<BC_, 320, FW_SMEM>>>(x);
    k_mul  <<<MODES_, 256>>>();
    k_invwh<<<BO_, 256, IW_SMEM>>>();
    k_zero <<<(B_*CO_*N_*16)/256, 256>>>((float4*)out);
    k_bc   <<<PS_/8, 256>>>(out);
}

// round 9
// speedup vs baseline: 2.5980x; 1.0812x over previous
#include <cuda_runtime.h>
#include <cstddef>

#define B_   16
#define CO_  64
#define N_   128
#define HW_  16384
#define MODES_ 400
#define BC_  1024
#define BO_  1024
#define NC_  73
#define NK_  65
#define PS_  (N_*NK_)      // 8320
#define FW_SMEM  98304     // k_fwd dynamic smem bytes
#define IW_SMEM  52640     // k_invwh dynamic smem bytes
#define WT_SMEM  51328     // k_wt dynamic smem bytes

typedef unsigned long long u64;
__device__ __forceinline__ u64 pack2(float lo, float hi) {
    u64 r; asm("mov.b64 %0, {%1,%2};" : "=l"(r) : "f"(lo), "f"(hi)); return r;
}
__device__ __forceinline__ float2 unpack2(u64 v) {
    float2 f; asm("mov.b64 {%0,%1}, %2;" : "=f"(f.x), "=f"(f.y) : "l"(v)); return f;
}
__device__ __forceinline__ u64 fma2(u64 a, u64 b, u64 c) {
    u64 d; asm("fma.rn.f32x2 %0, %1, %2, %3;" : "=l"(d) : "l"(a), "l"(b), "l"(c)); return d;
}

__device__ float  g_Xh[(size_t)MODES_*BC_];    // [mode][bc]
__device__ float  g_Z [(size_t)MODES_*BO_];    // [mode][bo]
__device__ float2 g_W2[(size_t)MODES_*4096];   // [mode][i] = (Wp, Wm)
__device__ float  g_buf1[(size_t)BO_*PS_];

__constant__ float GK[9] = {
    1.3383062e-04f, 4.4318606e-03f, 5.3991128e-02f, 2.4197145e-01f,
    3.9894348e-01f, 2.4197145e-01f, 5.3991128e-02f, 4.4318606e-03f,
    1.3383062e-04f
};

__device__ __forceinline__ void fill_tabs_n(float* ct, float* st, int nthr) {
    const float w = 6.283185307179586f / 128.0f;
    for (int t = threadIdx.x; t < 128; t += nthr) {
        float s, c;
        sincosf(w * (float)t, &s, &c);
        ct[t] = c; st[t] = s;
    }
}

// ---------------------------------------------------------------------------
// K0: transpose + fold weights once: g_W2[m][i] = (0.5(w+wn), 0.5(w-wn))
// ---------------------------------------------------------------------------
__global__ void __launch_bounds__(256) k_wt(const float* __restrict__ w1) {
    extern __shared__ float ws[];            // [32][401]
    int i0 = blockIdx.x * 32;
    for (int idx = threadIdx.x; idx < 32*400; idx += 256) {
        int r = idx / 400, m = idx - r*400;
        ws[r*401 + m] = w1[(size_t)(i0 + r)*400 + m];
    }
    __syncthreads();
    for (int idx = threadIdx.x; idx < 12800; idx += 256) {
        int m = idx >> 5, r = idx & 31;
        int m1 = m / 20, m2 = m - m1*20;
        int mn = ((20 - m1) % 20) * 20 + ((20 - m2) % 20);
        float w  = ws[r*401 + m];
        float wn = ws[r*401 + mn];
        g_W2[(size_t)m*4096 + i0 + r] = make_float2(0.5f*(w+wn), 0.5f*(w-wn));
    }
}

// ---------------------------------------------------------------------------
// K1: forward truncated DHT. Stage1 = packed-f32x2 GEMM; stage2 = packed
// contraction over interleaved TT=(cos,-sin), FF=(F1,F2). Out: g_Xh[mode][bc].
// ---------------------------------------------------------------------------
__global__ void __launch_bounds__(320) k_fwd(const float* __restrict__ x) {
    extern __shared__ float sm[];
    float* ct = sm;             // 128
    float* st = sm + 128;       // 128
    float* CT = sm + 256;       // 64*20
    float* ST = CT + 1280;      // 64*20
    float* xp = ST + 1280;      // 128*65
    float* xm = xp + 8320;      // 128*65
    float* U  = xm + 8320;      // 128*20
    float* V  = U + 2560;       // 128*20
    float2* FF = (float2*)xp;   // overlay after GEMM ([64][20] pairs)
    float2* TT = (float2*)U;    // overlay after F-build ([20][65] pairs)

    int tid = threadIdx.x;
    int bc  = blockIdx.x;
    const float* xb = x + (size_t)bc * HW_;

    fill_tabs_n(ct, st, 320);
    __syncthreads();

    for (int idx = tid; idx < 1280; idx += 320) {
        int q = idx / 20, k2 = idx - q*20;
        if (q == 0) { CT[idx] = 1.f; ST[idx] = 0.f; }
        else {
            int t = (q * k2) & 127;
            CT[idx] = ct[t]; ST[idx] = st[t];
        }
    }
    for (int idx = tid; idx < 8192; idx += 320) {
        int r = idx >> 6, q = idx & 63;
        const float* row = xb + r * 128;
        if (q == 0) { xp[r*65] = row[0]; xm[r*65] = row[64]; }
        else {
            float a = row[q], b = row[128 - q];
            xp[r*65 + q] = a + b; xm[r*65 + q] = a - b;
        }
    }
    __syncthreads();

    {   // stage1 GEMM, packed f32x2
        int ty = tid & 31, tx = tid >> 5;
        int isU = (tx < 5);
        int c0  = (isU ? tx : tx - 5) * 4;      // 0,4,8,12,16 (even)
        const float* A  = isU ? xp : xm;
        const float* Bm = isU ? CT : ST;
        u64 z = pack2(0.f, 0.f);
        u64 acc01[4] = {z,z,z,z}, acc23[4] = {z,z,z,z};
#pragma unroll 4
        for (int q = 0; q < 64; ++q) {
            u64 b01 = *(const u64*)(Bm + q*20 + c0);
            u64 b23 = *(const u64*)(Bm + q*20 + c0 + 2);
#pragma unroll
            for (int i = 0; i < 4; ++i) {
                float a = A[(ty + 32*i)*65 + q];
                u64 aa = pack2(a, a);
                acc01[i] = fma2(aa, b01, acc01[i]);
                acc23[i] = fma2(aa, b23, acc23[i]);
            }
        }
        float* O = isU ? U : V;
#pragma unroll
        for (int i = 0; i < 4; ++i) {
            float pm = isU ? xm[(ty + 32*i)*65] : 0.f;
            float2 f01 = unpack2(acc01[i]);
            float2 f23 = unpack2(acc23[i]);
            float* o = O + (ty + 32*i)*20 + c0;
            o[0] = f01.x + pm; o[1] = f01.y - pm;
            o[2] = f23.x + pm; o[3] = f23.y - pm;
        }
    }
    __syncthreads();

    // F build (E-fold + parity) -> FF interleaved (overlays xp)
    for (int idx = tid; idx < 1280; idx += 320) {
        int n = idx / 20, k2 = idx - n*20;
        float cd = ct[k2], sd = st[k2];
        float f1, f2;
        if (n == 0) {
            f1 = U[0*20+k2]  - (sd*U[127*20+k2] + cd*V[127*20+k2]);
            f2 = U[64*20+k2] - (sd*U[63*20+k2]  + cd*V[63*20+k2]);
        } else {
            int nm = n - 1, nn = 128 - n, nnm = 127 - n;
            float e1a = U[n*20+k2]  - (sd*U[nm*20+k2]  + cd*V[nm*20+k2]);
            float e2a = V[n*20+k2]  + (cd*U[nm*20+k2]  - sd*V[nm*20+k2]);
            float e1b = U[nn*20+k2] - (sd*U[nnm*20+k2] + cd*V[nnm*20+k2]);
            float e2b = V[nn*20+k2] + (cd*U[nnm*20+k2] - sd*V[nnm*20+k2]);
            f1 = e1a + e1b;
            f2 = e2a - e2b;
        }
        FF[n*20 + k2] = make_float2(f1, f2);
    }
    __syncthreads();

    // TT build (overlays U/V): (cos, -sin); n=0: (1, +/-1)
    for (int idx = tid; idx < 1300; idx += 320) {
        int k1 = idx / 65, n = idx - k1*65;
        if (n == 0)      TT[idx] = make_float2(1.f, (k1 & 1) ? -1.f : 1.f);
        else if (n < 64) { int t = (k1*n) & 127; TT[idx] = make_float2(ct[t], -st[t]); }
    }
    __syncthreads();

    {   // stage2: packed contraction
        const u64* TT64 = (const u64*)TT;
        const u64* FF64 = (const u64*)FF;
        for (int o = tid; o < 400; o += 320) {
            int k1 = o % 20, k2 = o / 20;
            u64 acc2 = pack2(0.f, 0.f);
#pragma unroll 8
            for (int n = 0; n < 64; ++n)
                acc2 = fma2(TT64[k1*65 + n], FF64[n*20 + k2], acc2);
            float2 f = unpack2(acc2);
            g_Xh[(size_t)(k1*20 + k2)*BC_ + bc] = f.x + f.y;
        }
    }
}

// ---------------------------------------------------------------------------
// K2: folded compl_mul2d, packed f32x2, fully coalesced.
// ---------------------------------------------------------------------------
__global__ void __launch_bounds__(256) k_mul(void) {
    __shared__ __align__(16) float X2[2048];   // [b*128 + i*2] = (X, Xneg)
    __shared__ __align__(16) float W2[8192];   // [i*128 + o*2] = (Wp, Wm)
    int m  = blockIdx.x;
    int m1 = m / 20, m2 = m % 20;
    int mn = ((20 - m1) % 20) * 20 + ((20 - m2) % 20);

    for (int i = threadIdx.x; i < 1024; i += 256) {
        X2[i*2]     = g_Xh[(size_t)m  * BC_ + i];
        X2[i*2 + 1] = g_Xh[(size_t)mn * BC_ + i];
    }
    for (int i = threadIdx.x; i < 4096; i += 256)
        ((float2*)W2)[i] = g_W2[(size_t)m*4096 + i];
    __syncthreads();

    for (int p = threadIdx.x; p < 1024; p += 256) {
        int b = p >> 6, o = p & 63;
        const u64* x2 = (const u64*)X2 + b*64;
        const u64* w2 = (const u64*)W2 + o;
        u64 acc2 = pack2(0.f, 0.f);
#pragma unroll 8
        for (int i = 0; i < 64; ++i)
            acc2 = fma2(x2[i], w2[i*64], acc2);
        float2 f = unpack2(acc2);
        g_Z[(size_t)m * BO_ + p] = f.x + f.y;
    }
}

// ---------------------------------------------------------------------------
// K3: FUSED inverse transform + W-blur(+mask) + H-blur. One block per (b,o).
// smem floats: ct[128] st[128] Zs[420] AB[1533 float2] pl[9417]
// ---------------------------------------------------------------------------
__global__ void __launch_bounds__(256) k_invwh(void) {
    extern __shared__ float sm[];
    float*  ct = sm;
    float*  st = sm + 128;
    float*  Zs = sm + 256;          // [20][21] padded
    float2* AB = (float2*)(sm + 676);   // [21][73] pairs (A,B)
    float*  pl = sm + 3742;         // stride 129, 73 cols
    float*  G1 = pl;
    float*  G2 = pl + 1460;
    float*  P1 = pl + 2920;
    float*  P2 = pl + 4380;

    int tid = threadIdx.x;
    int bo  = blockIdx.x;
    fill_tabs_n(ct, st, 256);
    for (int i = tid; i < 400; i += 256) {
        int m1 = i / 20, m2 = i - m1*20;
        Zs[m1*21 + m2] = g_Z[(size_t)i * BO_ + bo];
    }
    __syncthreads();

    // phase A: m1-register-tiled (4 per thread)
    const float inv = 6.103515625e-05f;
    for (int task = tid; task < 365; task += 256) {
        int j = task / 5, g = task - j*5;
        int m1b = g * 4;
        int n2 = (j < 37) ? j : j + 55;
        float a0=0.f,a1=0.f,a2=0.f,a3=0.f;
        float b0=0.f,b1=0.f,b2=0.f,b3=0.f;
        int t = 0;
#pragma unroll
        for (int m2 = 0; m2 < 20; ++m2) {
            float c = ct[t], s = st[t];
            float z0 = Zs[(m1b+0)*21 + m2];
            float z1 = Zs[(m1b+1)*21 + m2];
            float z2 = Zs[(m1b+2)*21 + m2];
            float z3 = Zs[(m1b+3)*21 + m2];
            a0 += z0*c; b0 += z0*s;
            a1 += z1*c; b1 += z1*s;
            a2 += z2*c; b2 += z2*s;
            a3 += z3*c; b3 += z3*s;
            t = (t + n2) & 127;
        }
        float cb = ct[n2], sb = st[n2];
        float ga[4] = {a0*inv, a1*inv, a2*inv, a3*inv};
        float gb[4] = {b0*inv, b1*inv, b2*inv, b3*inv};
#pragma unroll
        for (int u = 0; u < 4; ++u) {
            int m1 = m1b + u;
            G1[m1*73+j] = ga[u]; G2[m1*73+j] = gb[u];
            P1[m1*73+j] = cb*ga[u] - sb*gb[u];
            P2[m1*73+j] = sb*ga[u] + cb*gb[u];
        }
    }
    __syncthreads();

    // E-fold into interleaved AB (separate region; G..P overlay pl)
    for (int idx = tid; idx < 1533; idx += 256) {
        int m = idx / 73, j = idx - m*73;
        float a = 0.f, b = 0.f;
        if (m < 20) { a = G1[m*73+j]; b = G2[m*73+j]; }
        if (m > 0)  { a -= P2[(m-1)*73+j]; b += P1[(m-1)*73+j]; }
        AB[idx] = make_float2(a, b);
    }
    __syncthreads();

    // stage2: packed f32x2, parity-paired outputs -> pl
    {
        int n1p   = tid & 63;
        int chunk = tid >> 6;
        u64 cs[21];
#pragma unroll
        for (int m = 0; m < 21; ++m) {
            int tt = (n1p * m) & 127;
            cs[m] = pack2(ct[tt], st[tt]);
        }
        const u64* AB64 = (const u64*)AB;
        for (int j = chunk; j < 73; j += 4) {
            u64 acc2 = pack2(0.f, 0.f);
#pragma unroll
            for (int m = 0; m < 21; ++m)
                acc2 = fma2(cs[m], AB64[m*73 + j], acc2);
            float2 f = unpack2(acc2);
            pl[j*129 + n1p] = f.x - f.y;
            pl[j*129 + ((128 - n1p) & 127)] = f.x + f.y;
        }
    }
    // row n1=64 (never touched above): alternating sum of A
    for (int j = tid; j < 73; j += 256) {
        float s = 0.f;
#pragma unroll
        for (int m = 0; m < 21; ++m) {
            float a = AB[m*73 + j].x;
            s += (m & 1) ? -a : a;
        }
        pl[j*129 + 64] = s;
    }
    __syncthreads();

    // W-blur (+mask): sliding window per segment, in-place to 65 cols
    {
        int r = tid & 127, seg = tid >> 7;
        float acc[33];
        float win[9];
        if (seg == 0) {
#pragma unroll
            for (int k = 0; k < 9; ++k) {
                int p = k - 4; p = p < 0 ? 0 : p;
                win[k] = pl[p*129 + r];
            }
            for (int j = 0; j < 33; ++j) {
                float a = 0.f;
#pragma unroll
                for (int k = 0; k < 9; ++k) a += GK[k] * win[k];
                acc[j] = a;
#pragma unroll
                for (int k = 0; k < 8; ++k) win[k] = win[k+1];
                win[8] = pl[(j + 5)*129 + r];
            }
        } else {
#pragma unroll
            for (int k = 0; k < 9; ++k)
                win[k] = pl[(37 + k)*129 + r];
            for (int q = 0; q < 32; ++q) {
                float a = 0.f;
#pragma unroll
                for (int k = 0; k < 9; ++k) a += GK[k] * win[k];
                acc[q] = a;
#pragma unroll
                for (int k = 0; k < 8; ++k) win[k] = win[k+1];
                int pn = 46 + q; pn = pn > 72 ? 72 : pn;
                win[8] = pl[pn*129 + r];
            }
        }
        __syncthreads();
        if (seg == 0) {
            for (int j = 0; j < 33; ++j) pl[j*129 + r] = acc[j];
        } else {
            for (int q = 0; q < 32; ++q) pl[(33 + q)*129 + r] = acc[q];
        }
    }
    __syncthreads();

    // H-blur: sliding window along r, store direct to global
    {
        float* out = g_buf1 + (size_t)bo * PS_;
        for (int task = tid; task < 260; task += 256) {
            int seg = task / 65, j = task - seg*65;
            int r0 = seg * 32;
            float win[9];
#pragma unroll
            for (int k = 0; k < 9; ++k) {
                int rr = r0 + k - 4;
                rr = rr < 0 ? 0 : rr;
                win[k] = pl[j*129 + rr];
            }
            for (int q = 0; q < 32; ++q) {
                float a = 0.f;
#pragma unroll
                for (int k = 0; k < 9; ++k) a += GK[k] * win[k];
                out[(r0 + q)*65 + j] = a;
#pragma unroll
                for (int k = 0; k < 8; ++k) win[k] = win[k+1];
                int rn = r0 + q + 5; rn = rn > 127 ? 127 : rn;
                win[8] = pl[j*129 + rn];
            }
        }
    }
}

// K4: zero cols 32..95 of every output row (float4).
__global__ void __launch_bounds__(256) k_zero(float4* __restrict__ out) {
    int idx = blockIdx.x * 256 + threadIdx.x;
    int row = idx >> 4, q = (idx & 15) + 8;
    out[(size_t)row * 32 + q] = make_float4(0.f, 0.f, 0.f, 0.f);
}

// K5: FUSED B-blur + C-blur over [16][64][8-pos] tile; expands to output.
__global__ void __launch_bounds__(256) k_bc(float* __restrict__ out) {
    __shared__ float t[16*520];
    __shared__ int rr8[8], ww8[8];
    int tid = threadIdx.x;
    int p0  = blockIdx.x * 8;

    if (tid < 8) {
        int pos = p0 + tid;
        int r = pos / 65, j = pos - r*65;
        rr8[tid] = r;
        ww8[tid] = (j < 33) ? j : j + 63;
    }
    for (int idx = tid; idx < 8192; idx += 256) {
        int b = idx >> 9, rem = idx & 511;
        int c = rem >> 3, p = rem & 7;
        t[b*520 + rem] = g_buf1[(size_t)b*(CO_*PS_) + (size_t)c*PS_ + p0 + p];
    }
    __syncthreads();

    for (int task = tid; task < 512; task += 256) {
        float v[16], o[16];
#pragma unroll
        for (int b = 0; b < 16; ++b) v[b] = t[b*520 + task];
#pragma unroll
        for (int b = 0; b < 16; ++b) {
            float a = 0.f;
#pragma unroll
            for (int k = 0; k < 9; ++k) {
                int bb = b + k - 4;
                bb = bb < 0 ? 0 : (bb > 15 ? 15 : bb);
                a += GK[k] * v[bb];
            }
            o[b] = a;
        }
#pragma unroll
        for (int b = 0; b < 16; ++b) t[b*520 + task] = o[b];
    }
    __syncthreads();

    float cres[32];
    {
        int b = tid >> 4, p = (tid >> 1) & 7, half = tid & 1;
        const float* line = t + b*520 + p;
        int cbeg = half * 32;
        float win[9];
#pragma unroll
        for (int k = 0; k < 9; ++k) {
            int c = cbeg + k - 4; c = c < 0 ? 0 : (c > 63 ? 63 : c);
            win[k] = line[c*8];
        }
#pragma unroll
        for (int q = 0; q < 32; ++q) {
            float a = 0.f;
#pragma unroll
            for (int k = 0; k < 9; ++k) a += GK[k] * win[k];
            cres[q] = a;
#pragma unroll
            for (int k = 0; k < 8; ++k) win[k] = win[k+1];
            int cn = cbeg + q + 5; cn = cn > 63 ? 63 : cn;
            win[8] = line[cn*8];
        }
    }
    __syncthreads();
    {
        int b = tid >> 4, p = (tid >> 1) & 7, half = tid & 1;
        float* line = t + b*520 + p;
#pragma unroll
        for (int q = 0; q < 32; ++q) line[(half*32 + q)*8] = cres[q];
    }
    __syncthreads();

    for (int idx = tid; idx < 8192; idx += 256) {
        int b = idx >> 9, rem = idx & 511;
        int c = rem >> 3, p = rem & 7;
        out[(size_t)b*(CO_*HW_) + (size_t)c*HW_ + rr8[p]*128 + ww8[p]]
            = t[b*520 + rem];
    }
}

extern "C" void kernel_launch(void* const* d_in, const int* in_sizes, int n_in,
                              void* d_out, int out_size) {
    (void)in_sizes; (void)n_in; (void)out_size;
    const float* x  = (const float*)d_in[0];
    const float* w1 = (const float*)d_in[1];
    float* out = (float*)d_out;

    cudaFuncSetAttribute(k_fwd, cudaFuncAttributeMaxDynamicSharedMemorySize,
                         FW_SMEM);
    cudaFuncSetAttribute(k_invwh, cudaFuncAttributeMaxDynamicSharedMemorySize,
                         IW_SMEM);
    cudaFuncSetAttribute(k_wt, cudaFuncAttributeMaxDynamicSharedMemorySize,
                         WT_SMEM);
    k_wt   <<<128, 256, WT_SMEM>>>(w1);
    k_fwd  <<<BC_, 320, FW_SMEM>>>(x);
    k_mul  <<<MODES_, 256>>>();
    k_invwh<<<BO_, 256, IW_SMEM>>>();
    k_zero <<<(B_*CO_*N_*16)/256, 256>>>((float4*)out);
    k_bc   <<<PS_/8, 256>>>(out);
}